// round 2
// baseline (speedup 1.0000x reference)
#include <cuda_runtime.h>

#define B_  2
#define S_  2048
#define D_  1024
#define H_  16
#define HD_ 64
#define MTOT (B_*S_)          // 4096
#define NELEM (B_*S_*D_)      // 4194304
#define PITCH 68              // smem row pitch (multiple of 4 -> float4 aligned)

// Scratch (allocation-free rule: __device__ globals)
__device__ __align__(16) float g_Q[NELEM];     // [B,H,S,HD], pre-scaled by HD^-0.5
__device__ __align__(16) float g_K[NELEM];     // [B,H,S,HD]
__device__ __align__(16) float g_V[NELEM];     // [B,H,S,HD]
__device__ __align__(16) float g_attn[NELEM];  // [B,S,D]

// ---------------------------------------------------------------------------
// SGEMM: C[m,n] = sum_k A[m,k] * W[n,k]   (A: MxK row-major, W: NxK row-major)
// M=4096, N=1024, K=1024. 128x128 block, BK=8, 256 threads, 8x8 per thread.
// MODE 0: QKV projection. blockIdx.z selects W0/W1/W2 and g_Q/g_K/g_V output
//         (head layout [B,H,S,HD]); z==0 output scaled by 0.125 (= HD^-0.5).
// MODE 1: plain C = A@W0^T + bias into Cout.
// ---------------------------------------------------------------------------
template<int MODE>
__global__ __launch_bounds__(256) void sgemm_kernel(
    const float* __restrict__ A,
    const float* __restrict__ W0,
    const float* __restrict__ W1,
    const float* __restrict__ W2,
    const float* __restrict__ bias,
    float* __restrict__ Cout)
{
    const int Kd = 1024;
    __shared__ float As[8][128];
    __shared__ float Bs[8][128];

    const int tid = threadIdx.x;
    const int tx = tid & 15;        // 0..15  (N direction)
    const int ty = tid >> 4;        // 0..15  (M direction)
    const int m0 = blockIdx.y * 128;
    const int n0 = blockIdx.x * 128;

    const float* Bmat;
    if (MODE == 0) Bmat = (blockIdx.z == 0) ? W0 : (blockIdx.z == 1 ? W1 : W2);
    else           Bmat = W0;

    // tile loaders: each thread loads one float4 of A and one of B per k-step
    const int lrow = tid >> 1;            // 0..127
    const int lk4  = (tid & 1) << 2;      // 0 or 4
    const float* Aload = A    + (size_t)(m0 + lrow) * Kd + lk4;
    const float* Bload = Bmat + (size_t)(n0 + lrow) * Kd + lk4;

    float acc[8][8];
    #pragma unroll
    for (int i = 0; i < 8; i++)
        #pragma unroll
        for (int j = 0; j < 8; j++) acc[i][j] = 0.f;

    for (int kt = 0; kt < Kd; kt += 8) {
        float4 av = *(const float4*)(Aload + kt);
        float4 bv = *(const float4*)(Bload + kt);
        As[lk4+0][lrow] = av.x; As[lk4+1][lrow] = av.y;
        As[lk4+2][lrow] = av.z; As[lk4+3][lrow] = av.w;
        Bs[lk4+0][lrow] = bv.x; Bs[lk4+1][lrow] = bv.y;
        Bs[lk4+2][lrow] = bv.z; Bs[lk4+3][lrow] = bv.w;
        __syncthreads();

        #pragma unroll
        for (int kk = 0; kk < 8; kk++) {
            float a[8], b[8];
            *(float4*)&a[0] = *(const float4*)&As[kk][ty*4];
            *(float4*)&a[4] = *(const float4*)&As[kk][64 + ty*4];
            *(float4*)&b[0] = *(const float4*)&Bs[kk][tx*4];
            *(float4*)&b[4] = *(const float4*)&Bs[kk][64 + tx*4];
            #pragma unroll
            for (int i = 0; i < 8; i++)
                #pragma unroll
                for (int j = 0; j < 8; j++)
                    acc[i][j] = fmaf(a[i], b[j], acc[i][j]);
        }
        __syncthreads();
    }

    // epilogue
    const float scale = (MODE == 0 && blockIdx.z == 0) ? 0.125f : 1.0f;
    float* dst0 = nullptr;
    if (MODE == 0) dst0 = (blockIdx.z == 0) ? g_Q : (blockIdx.z == 1 ? g_K : g_V);

    #pragma unroll
    for (int ih = 0; ih < 2; ih++) {
        #pragma unroll
        for (int i = 0; i < 4; i++) {
            const int m = m0 + ih*64 + ty*4 + i;
            #pragma unroll
            for (int jh = 0; jh < 2; jh++) {
                const int n = n0 + jh*64 + tx*4;
                float4 v;
                v.x = acc[ih*4+i][jh*4+0] * scale;
                v.y = acc[ih*4+i][jh*4+1] * scale;
                v.z = acc[ih*4+i][jh*4+2] * scale;
                v.w = acc[ih*4+i][jh*4+3] * scale;
                if (MODE == 0) {
                    const int b = m >> 11, s = m & 2047;
                    const int h = n >> 6,  hd = n & 63;
                    *(float4*)&dst0[(((b*H_ + h)*S_) + s)*HD_ + hd] = v;
                } else {
                    const float4 bb = *(const float4*)&bias[n];
                    v.x += bb.x; v.y += bb.y; v.z += bb.z; v.w += bb.w;
                    *(float4*)&Cout[(size_t)m * 1024 + n] = v;
                }
            }
        }
    }
}

// ---------------------------------------------------------------------------
// Flash attention (fp32): one block = one (b,h) and 64 queries.
// Smem: Qs[d][q], Ks[d][k], Vs[k][d], Ps[k][q], all pitch PITCH (=68, 16B-aligned rows).
// 256 threads (16x16), each owns 4 queries x 4 cols.
// ---------------------------------------------------------------------------
__global__ __launch_bounds__(256) void attn_kernel(const int* __restrict__ Mmask)
{
    extern __shared__ float sm[];
    float* Qs = sm;                   // 64*PITCH
    float* Ks = sm + 64*PITCH;        // 64*PITCH
    float* Vs = sm + 2*64*PITCH;      // 64*PITCH
    float* Ps = sm + 3*64*PITCH;      // 64*PITCH

    const int tid = threadIdx.x;
    const int tx = tid & 15;       // key/dim direction
    const int ty = tid >> 4;       // query direction
    const int bh = blockIdx.y;     // 0..31
    const int b = bh >> 4, h = bh & 15;
    const int q0 = blockIdx.x << 6;

    const float* Qg = g_Q + (size_t)(bh*S_ + q0) * HD_;
    const int mbase = (b*S_ + q0) * S_;

    // load Q tile transposed: Qs[d*PITCH + q]
    #pragma unroll
    for (int it = 0; it < 4; it++) {
        const int idx = tid + it*256;       // 0..1023 float4 slots
        const int r = idx >> 4;             // query row 0..63
        const int c = (idx & 15) << 2;      // dim 0,4,...,60
        float4 v = *(const float4*)(Qg + r*HD_ + c);
        Qs[(c+0)*PITCH + r] = v.x;
        Qs[(c+1)*PITCH + r] = v.y;
        Qs[(c+2)*PITCH + r] = v.z;
        Qs[(c+3)*PITCH + r] = v.w;
    }

    float m_i[4], l_i[4], acc[4][4];
    #pragma unroll
    for (int qi = 0; qi < 4; qi++) {
        m_i[qi] = -1e30f;
        l_i[qi] = 0.f;
        #pragma unroll
        for (int di = 0; di < 4; di++) acc[qi][di] = 0.f;
    }

    for (int k0 = 0; k0 < S_; k0 += 64) {
        __syncthreads();   // previous iteration's Ks/Vs/Ps readers done
        const float* Kg = g_K + (size_t)(bh*S_ + k0) * HD_;
        const float* Vg = g_V + (size_t)(bh*S_ + k0) * HD_;
        #pragma unroll
        for (int it = 0; it < 4; it++) {
            const int idx = tid + it*256;
            const int r = idx >> 4;
            const int c = (idx & 15) << 2;
            float4 kv = *(const float4*)(Kg + r*HD_ + c);
            Ks[(c+0)*PITCH + r] = kv.x;
            Ks[(c+1)*PITCH + r] = kv.y;
            Ks[(c+2)*PITCH + r] = kv.z;
            Ks[(c+3)*PITCH + r] = kv.w;
            float4 vv = *(const float4*)(Vg + r*HD_ + c);
            *(float4*)&Vs[r*PITCH + c] = vv;
        }
        __syncthreads();

        // scores: s[qi][kj] = sum_d Q[q,d]*K[k,d]   (Q pre-scaled)
        float s[4][4];
        #pragma unroll
        for (int qi = 0; qi < 4; qi++)
            #pragma unroll
            for (int kj = 0; kj < 4; kj++) s[qi][kj] = 0.f;

        #pragma unroll 8
        for (int d = 0; d < 64; d++) {
            const float4 qa = *(const float4*)&Qs[d*PITCH + ty*4];
            const float4 kb = *(const float4*)&Ks[d*PITCH + tx*4];
            const float a[4] = {qa.x, qa.y, qa.z, qa.w};
            const float bb[4] = {kb.x, kb.y, kb.z, kb.w};
            #pragma unroll
            for (int qi = 0; qi < 4; qi++)
                #pragma unroll
                for (int kj = 0; kj < 4; kj++)
                    s[qi][kj] = fmaf(a[qi], bb[kj], s[qi][kj]);
        }

        // mask + online softmax
        #pragma unroll
        for (int qi = 0; qi < 4; qi++) {
            const int4 mv = *(const int4*)&Mmask[mbase + (ty*4+qi)*S_ + k0 + tx*4];
            if (mv.x == 0) s[qi][0] = -1e9f;
            if (mv.y == 0) s[qi][1] = -1e9f;
            if (mv.z == 0) s[qi][2] = -1e9f;
            if (mv.w == 0) s[qi][3] = -1e9f;

            float mx = fmaxf(fmaxf(s[qi][0], s[qi][1]), fmaxf(s[qi][2], s[qi][3]));
            #pragma unroll
            for (int o = 8; o > 0; o >>= 1)
                mx = fmaxf(mx, __shfl_xor_sync(0xffffffffu, mx, o, 16));

            const float mnew  = fmaxf(m_i[qi], mx);
            const float alpha = __expf(m_i[qi] - mnew);
            m_i[qi] = mnew;

            float rs = 0.f;
            #pragma unroll
            for (int kj = 0; kj < 4; kj++) {
                const float p = __expf(s[qi][kj] - mnew);
                s[qi][kj] = p;
                rs += p;
            }
            #pragma unroll
            for (int o = 8; o > 0; o >>= 1)
                rs += __shfl_xor_sync(0xffffffffu, rs, o, 16);

            l_i[qi] = l_i[qi]*alpha + rs;
            #pragma unroll
            for (int di = 0; di < 4; di++) acc[qi][di] *= alpha;
            #pragma unroll
            for (int kj = 0; kj < 4; kj++)
                Ps[(tx*4+kj)*PITCH + ty*4 + qi] = s[qi][kj];
        }
        __syncthreads();

        // acc += P @ V
        #pragma unroll 8
        for (int kk = 0; kk < 64; kk++) {
            const float4 pa = *(const float4*)&Ps[kk*PITCH + ty*4];
            const float4 vb = *(const float4*)&Vs[kk*PITCH + tx*4];
            const float a[4] = {pa.x, pa.y, pa.z, pa.w};
            const float bb[4] = {vb.x, vb.y, vb.z, vb.w};
            #pragma unroll
            for (int qi = 0; qi < 4; qi++)
                #pragma unroll
                for (int di = 0; di < 4; di++)
                    acc[qi][di] = fmaf(a[qi], bb[di], acc[qi][di]);
        }
    }

    // normalize + write to [B,S,D]
    #pragma unroll
    for (int qi = 0; qi < 4; qi++) {
        const float inv = 1.0f / l_i[qi];
        float4 v;
        v.x = acc[qi][0]*inv; v.y = acc[qi][1]*inv;
        v.z = acc[qi][2]*inv; v.w = acc[qi][3]*inv;
        *(float4*)&g_attn[(size_t)(b*S_ + q0 + ty*4 + qi)*D_ + h*HD_ + tx*4] = v;
    }
}

// ---------------------------------------------------------------------------
extern "C" void kernel_launch(void* const* d_in, const int* in_sizes, int n_in,
                              void* d_out, int out_size)
{
    const float* x  = (const float*)d_in[0];
    const int*   Mm = (const int*)  d_in[1];
    const float* Wq = (const float*)d_in[2];
    const float* Wk = (const float*)d_in[3];
    const float* Wv = (const float*)d_in[4];
    const float* Wo = (const float*)d_in[5];
    const float* bo = (const float*)d_in[6];
    float* out = (float*)d_out;

    float* attnPtr = nullptr;
    cudaGetSymbolAddress((void**)&attnPtr, g_attn);

    const int attn_smem = 4 * 64 * PITCH * (int)sizeof(float);  // 69632 B
    cudaFuncSetAttribute(attn_kernel,
                         cudaFuncAttributeMaxDynamicSharedMemorySize, attn_smem);

    // 1) QKV projections (fused over gridDim.z)
    sgemm_kernel<0><<<dim3(8, 32, 3), 256>>>(x, Wq, Wk, Wv, nullptr, nullptr);
    // 2) masked flash attention -> g_attn [B,S,D]
    attn_kernel<<<dim3(S_/64, B_*H_), 256, attn_smem>>>(Mm);
    // 3) output projection + bias
    sgemm_kernel<1><<<dim3(8, 32, 1), 256>>>(attnPtr, Wo, Wo, Wo, bo, out);
}

// round 4
// speedup vs baseline: 1.3484x; 1.3484x over previous
#include <cuda_runtime.h>
#include <cuda_bf16.h>
#include <cstdint>

#define B_  2
#define S_  2048
#define D_  1024
#define H_  16
#define HD_ 64
#define NELEM (B_*S_*D_)      // 4194304
#define PITCH 68              // attn smem row pitch (float4-aligned)

// Scratch (allocation-free rule: __device__ globals)
__device__ __align__(16) float g_Q[NELEM];     // [B,H,S,HD], pre-scaled by HD^-0.5
__device__ __align__(16) float g_K[NELEM];     // [B,H,S,HD]
__device__ __align__(16) float g_V[NELEM];     // [B,H,S,HD]
__device__ __align__(16) float g_attn[NELEM];  // [B,S,D]
__device__ __align__(16) __nv_bfloat16 g_xhi[NELEM];      // activations hi
__device__ __align__(16) __nv_bfloat16 g_xlo[NELEM];      // activations lo
__device__ __align__(16) __nv_bfloat16 g_whi[4*D_*D_];    // Wq,Wk,Wv,Wo hi
__device__ __align__(16) __nv_bfloat16 g_wlo[4*D_*D_];    // Wq,Wk,Wv,Wo lo

// ===========================================================================
// PTX helpers (baseline PTX only: ldmatrix / mma.sync / cp.async — all OK
// under compute_103; NO tcgen05)
// ===========================================================================
__device__ __forceinline__ uint32_t smem_u32(const void* p) {
    uint32_t a;
    asm("{ .reg .u64 t; cvta.to.shared.u64 t, %1; cvt.u32.u64 %0, t; }"
        : "=r"(a) : "l"(p));
    return a;
}
__device__ __forceinline__ void cp16(uint32_t saddr, const void* g) {
    asm volatile("cp.async.cg.shared.global [%0], [%1], 16;"
                 :: "r"(saddr), "l"(g) : "memory");
}
__device__ __forceinline__ void ldm_x4(uint32_t* r, uint32_t addr) {
    asm volatile("ldmatrix.sync.aligned.m8n8.x4.shared.b16 {%0,%1,%2,%3}, [%4];"
        : "=r"(r[0]), "=r"(r[1]), "=r"(r[2]), "=r"(r[3]) : "r"(addr));
}
__device__ __forceinline__ void ldm_x2(uint32_t* r, uint32_t addr) {
    asm volatile("ldmatrix.sync.aligned.m8n8.x2.shared.b16 {%0,%1}, [%2];"
        : "=r"(r[0]), "=r"(r[1]) : "r"(addr));
}
__device__ __forceinline__ void mma_bf16(float* c, const uint32_t* a, const uint32_t* b) {
    asm volatile("mma.sync.aligned.m16n8k16.row.col.f32.bf16.bf16.f32 "
        "{%0,%1,%2,%3}, {%4,%5,%6,%7}, {%8,%9}, {%0,%1,%2,%3};"
        : "+f"(c[0]), "+f"(c[1]), "+f"(c[2]), "+f"(c[3])
        : "r"(a[0]), "r"(a[1]), "r"(a[2]), "r"(a[3]), "r"(b[0]), "r"(b[1]));
}

// fp32 -> hi/lo bf16 split (packed pair helper)
__device__ __forceinline__ void split2(float x, float y, uint32_t& h, uint32_t& l) {
    __nv_bfloat16 hx = __float2bfloat16(x);
    __nv_bfloat16 hy = __float2bfloat16(y);
    __nv_bfloat16 lx = __float2bfloat16(x - __bfloat162float(hx));
    __nv_bfloat16 ly = __float2bfloat16(y - __bfloat162float(hy));
    h = (uint32_t)__bfloat16_as_ushort(hx) | ((uint32_t)__bfloat16_as_ushort(hy) << 16);
    l = (uint32_t)__bfloat16_as_ushort(lx) | ((uint32_t)__bfloat16_as_ushort(ly) << 16);
}

// ---------------------------------------------------------------------------
// split kernels: fp32 -> (hi, lo) bf16
// ---------------------------------------------------------------------------
__global__ __launch_bounds__(256) void split_x_kernel(
    const float* __restrict__ src,
    __nv_bfloat16* __restrict__ hi, __nv_bfloat16* __restrict__ lo)
{
    const int i = (blockIdx.x * 256 + threadIdx.x) * 4;
    const float4 v = *(const float4*)(src + i);
    uint2 hv, lv;
    split2(v.x, v.y, hv.x, lv.x);
    split2(v.z, v.w, hv.y, lv.y);
    *(uint2*)(hi + i) = hv;
    *(uint2*)(lo + i) = lv;
}

__global__ __launch_bounds__(256) void split_w_kernel(
    const float* __restrict__ w0, const float* __restrict__ w1,
    const float* __restrict__ w2, const float* __restrict__ w3)
{
    const int wsel = blockIdx.y;
    const float* src = (wsel == 0) ? w0 : (wsel == 1) ? w1 : (wsel == 2) ? w2 : w3;
    const int i = (blockIdx.x * 256 + threadIdx.x) * 4;
    const float4 v = *(const float4*)(src + i);
    uint2 hv, lv;
    split2(v.x, v.y, hv.x, lv.x);
    split2(v.z, v.w, hv.y, lv.y);
    const size_t o = (size_t)wsel * D_ * D_ + i;
    *(uint2*)(g_whi + o) = hv;
    *(uint2*)(g_wlo + o) = lv;
}

// ===========================================================================
// HMMA GEMM: C[m,n] = sum_k A[m,k]*W[n,k]  (fp32 via 3-term bf16 split)
// M=4096 N=1024 K=1024. Block 128x128, 8 warps (warp tile 64x32), KC=32
// chunks, cp.async double buffer, smem pitch 40 bf16 (80B, ldmatrix
// conflict-free).
// MODE 0: z selects Wq/Wk/Wv; out -> g_Q/g_K/g_V [B,H,S,HD] (Q scaled 0.125)
// MODE 1: W = Wo (idx 3); out = A@Wo^T + bias -> Cout
// ===========================================================================
#define KC 32
#define NCH 32
#define AP 40                 // smem pitch in bf16 units
#define TILE_ELT (128*AP)     // bf16 elems per tile

template<int MODE>
__global__ __launch_bounds__(256) void tgemm_kernel(
    const __nv_bfloat16* __restrict__ Ahi_g,
    const __nv_bfloat16* __restrict__ Alo_g,
    const float* __restrict__ bias,
    float* __restrict__ Cout)
{
    extern __shared__ __nv_bfloat16 smem[];
    const uint32_t sb = smem_u32(smem);

    const int tid = threadIdx.x;
    const int wid = tid >> 5, lane = tid & 31;
    const int m0 = blockIdx.y * 128;
    const int n0 = blockIdx.x * 128;
    const int widx = (MODE == 0) ? blockIdx.z : 3;
    const __nv_bfloat16* Bhi_g = g_whi + (size_t)widx * D_ * D_;
    const __nv_bfloat16* Blo_g = g_wlo + (size_t)widx * D_ * D_;

    // cp.async per-thread slot: rows lrow0 and lrow0+64, 8 bf16 at lcol
    const int lrow0 = tid >> 2;
    const int lcol  = (tid & 3) * 8;

    // ldmatrix per-lane offsets
    const int arow  = (lane & 7) + ((lane >> 3) & 1) * 8;   // A row within 16
    const int akoff = ((lane >> 4) & 1) * 8;                // A k offset
    const int brow  = lane & 7;                             // B n row within 8
    const int bkoff = ((lane >> 3) & 1) * 8;                // B k offset
    const int wm = (wid & 1) * 64;
    const int wn = (wid >> 1) * 32;

    float acc[4][4][4];
    #pragma unroll
    for (int mt = 0; mt < 4; mt++)
        #pragma unroll
        for (int nt = 0; nt < 4; nt++)
            #pragma unroll
            for (int j = 0; j < 4; j++) acc[mt][nt][j] = 0.f;

    // ---- prefetch helper (macro-ish via lambda) ----
    auto prefetch = [&](int c) {
        const int buf = c & 1;
        const int kc = c * KC;
        const uint32_t s0 = sb + (uint32_t)(buf * 4 * TILE_ELT) * 2;
        const uint32_t soff = (uint32_t)(lrow0 * AP + lcol) * 2;
        {   // A hi
            const __nv_bfloat16* g = Ahi_g + (size_t)(m0 + lrow0) * 1024 + kc + lcol;
            cp16(s0 + 0 * TILE_ELT * 2 + soff, g);
            cp16(s0 + 0 * TILE_ELT * 2 + soff + 64 * AP * 2, g + 64 * 1024);
        }
        {   // A lo
            const __nv_bfloat16* g = Alo_g + (size_t)(m0 + lrow0) * 1024 + kc + lcol;
            cp16(s0 + 1 * TILE_ELT * 2 + soff, g);
            cp16(s0 + 1 * TILE_ELT * 2 + soff + 64 * AP * 2, g + 64 * 1024);
        }
        {   // B hi
            const __nv_bfloat16* g = Bhi_g + (size_t)(n0 + lrow0) * 1024 + kc + lcol;
            cp16(s0 + 2 * TILE_ELT * 2 + soff, g);
            cp16(s0 + 2 * TILE_ELT * 2 + soff + 64 * AP * 2, g + 64 * 1024);
        }
        {   // B lo
            const __nv_bfloat16* g = Blo_g + (size_t)(n0 + lrow0) * 1024 + kc + lcol;
            cp16(s0 + 3 * TILE_ELT * 2 + soff, g);
            cp16(s0 + 3 * TILE_ELT * 2 + soff + 64 * AP * 2, g + 64 * 1024);
        }
        asm volatile("cp.async.commit_group;" ::: "memory");
    };

    prefetch(0);

    for (int c = 0; c < NCH; c++) {
        if (c + 1 < NCH) {
            prefetch(c + 1);
            asm volatile("cp.async.wait_group 1;" ::: "memory");
        } else {
            asm volatile("cp.async.wait_group 0;" ::: "memory");
        }
        __syncthreads();

        const int buf = c & 1;
        const uint32_t base = sb + (uint32_t)(buf * 4 * TILE_ELT) * 2;
        const uint32_t aAhi = base;
        const uint32_t aAlo = base + (uint32_t)TILE_ELT * 2;
        const uint32_t aBhi = base + (uint32_t)TILE_ELT * 4;
        const uint32_t aBlo = base + (uint32_t)TILE_ELT * 6;

        #pragma unroll
        for (int ks = 0; ks < 2; ks++) {
            const int k0 = ks * 16;
            uint32_t bh[4][2], bl[4][2];
            #pragma unroll
            for (int nt = 0; nt < 4; nt++) {
                const uint32_t ba =
                    (uint32_t)((wn + nt * 8 + brow) * AP + k0 + bkoff) * 2;
                ldm_x2(bh[nt], aBhi + ba);
                ldm_x2(bl[nt], aBlo + ba);
            }
            #pragma unroll
            for (int mt = 0; mt < 4; mt++) {
                const uint32_t aa =
                    (uint32_t)((wm + mt * 16 + arow) * AP + k0 + akoff) * 2;
                uint32_t ah[4], al[4];
                ldm_x4(ah, aAhi + aa);
                ldm_x4(al, aAlo + aa);
                #pragma unroll
                for (int nt = 0; nt < 4; nt++) {
                    mma_bf16(acc[mt][nt], ah, bh[nt]);
                    mma_bf16(acc[mt][nt], ah, bl[nt]);
                    mma_bf16(acc[mt][nt], al, bh[nt]);
                }
            }
        }
        __syncthreads();
    }

    // ---- epilogue ----
    const int r_lo  = lane >> 2;          // 0..7
    const int coff  = (lane & 3) * 2;     // even column
    const float scale = (MODE == 0 && blockIdx.z == 0) ? 0.125f : 1.0f;
    float* dst0 = nullptr;
    if (MODE == 0) dst0 = (blockIdx.z == 0) ? g_Q : (blockIdx.z == 1 ? g_K : g_V);

    #pragma unroll
    for (int mt = 0; mt < 4; mt++) {
        const int r0 = m0 + wm + mt * 16 + r_lo;
        const int r1 = r0 + 8;
        #pragma unroll
        for (int nt = 0; nt < 4; nt++) {
            const int cg = n0 + wn + nt * 8 + coff;
            float2 v0 = make_float2(acc[mt][nt][0] * scale, acc[mt][nt][1] * scale);
            float2 v1 = make_float2(acc[mt][nt][2] * scale, acc[mt][nt][3] * scale);
            if (MODE == 0) {
                const int h = cg >> 6, hd = cg & 63;
                {
                    const int b = r0 >> 11, s = r0 & 2047;
                    *(float2*)&dst0[(((size_t)(b * H_ + h)) * S_ + s) * HD_ + hd] = v0;
                }
                {
                    const int b = r1 >> 11, s = r1 & 2047;
                    *(float2*)&dst0[(((size_t)(b * H_ + h)) * S_ + s) * HD_ + hd] = v1;
                }
            } else {
                const float2 bb = *(const float2*)&bias[cg];
                v0.x += bb.x; v0.y += bb.y;
                v1.x += bb.x; v1.y += bb.y;
                *(float2*)&Cout[(size_t)r0 * 1024 + cg] = v0;
                *(float2*)&Cout[(size_t)r1 * 1024 + cg] = v1;
            }
        }
    }
}

// ---------------------------------------------------------------------------
// Flash attention (fp32) — unchanged from passing R2 kernel.
// ---------------------------------------------------------------------------
__global__ __launch_bounds__(256) void attn_kernel(const int* __restrict__ Mmask)
{
    extern __shared__ float smf[];
    float* Qs = smf;
    float* Ks = smf + 64*PITCH;
    float* Vs = smf + 2*64*PITCH;
    float* Ps = smf + 3*64*PITCH;

    const int tid = threadIdx.x;
    const int tx = tid & 15;
    const int ty = tid >> 4;
    const int bh = blockIdx.y;
    const int b = bh >> 4, h = bh & 15;
    const int q0 = blockIdx.x << 6;

    const float* Qg = g_Q + (size_t)(bh*S_ + q0) * HD_;
    const int mbase = (b*S_ + q0) * S_;

    #pragma unroll
    for (int it = 0; it < 4; it++) {
        const int idx = tid + it*256;
        const int r = idx >> 4;
        const int c = (idx & 15) << 2;
        float4 v = *(const float4*)(Qg + r*HD_ + c);
        Qs[(c+0)*PITCH + r] = v.x;
        Qs[(c+1)*PITCH + r] = v.y;
        Qs[(c+2)*PITCH + r] = v.z;
        Qs[(c+3)*PITCH + r] = v.w;
    }

    float m_i[4], l_i[4], acc[4][4];
    #pragma unroll
    for (int qi = 0; qi < 4; qi++) {
        m_i[qi] = -1e30f;
        l_i[qi] = 0.f;
        #pragma unroll
        for (int di = 0; di < 4; di++) acc[qi][di] = 0.f;
    }

    for (int k0 = 0; k0 < S_; k0 += 64) {
        __syncthreads();
        const float* Kg = g_K + (size_t)(bh*S_ + k0) * HD_;
        const float* Vg = g_V + (size_t)(bh*S_ + k0) * HD_;
        #pragma unroll
        for (int it = 0; it < 4; it++) {
            const int idx = tid + it*256;
            const int r = idx >> 4;
            const int c = (idx & 15) << 2;
            float4 kv = *(const float4*)(Kg + r*HD_ + c);
            Ks[(c+0)*PITCH + r] = kv.x;
            Ks[(c+1)*PITCH + r] = kv.y;
            Ks[(c+2)*PITCH + r] = kv.z;
            Ks[(c+3)*PITCH + r] = kv.w;
            float4 vv = *(const float4*)(Vg + r*HD_ + c);
            *(float4*)&Vs[r*PITCH + c] = vv;
        }
        __syncthreads();

        float s[4][4];
        #pragma unroll
        for (int qi = 0; qi < 4; qi++)
            #pragma unroll
            for (int kj = 0; kj < 4; kj++) s[qi][kj] = 0.f;

        #pragma unroll 8
        for (int d = 0; d < 64; d++) {
            const float4 qa = *(const float4*)&Qs[d*PITCH + ty*4];
            const float4 kb = *(const float4*)&Ks[d*PITCH + tx*4];
            const float a[4] = {qa.x, qa.y, qa.z, qa.w};
            const float bb[4] = {kb.x, kb.y, kb.z, kb.w};
            #pragma unroll
            for (int qi = 0; qi < 4; qi++)
                #pragma unroll
                for (int kj = 0; kj < 4; kj++)
                    s[qi][kj] = fmaf(a[qi], bb[kj], s[qi][kj]);
        }

        #pragma unroll
        for (int qi = 0; qi < 4; qi++) {
            const int4 mv = *(const int4*)&Mmask[mbase + (ty*4+qi)*S_ + k0 + tx*4];
            if (mv.x == 0) s[qi][0] = -1e9f;
            if (mv.y == 0) s[qi][1] = -1e9f;
            if (mv.z == 0) s[qi][2] = -1e9f;
            if (mv.w == 0) s[qi][3] = -1e9f;

            float mx = fmaxf(fmaxf(s[qi][0], s[qi][1]), fmaxf(s[qi][2], s[qi][3]));
            #pragma unroll
            for (int o = 8; o > 0; o >>= 1)
                mx = fmaxf(mx, __shfl_xor_sync(0xffffffffu, mx, o, 16));

            const float mnew  = fmaxf(m_i[qi], mx);
            const float alpha = __expf(m_i[qi] - mnew);
            m_i[qi] = mnew;

            float rs = 0.f;
            #pragma unroll
            for (int kj = 0; kj < 4; kj++) {
                const float p = __expf(s[qi][kj] - mnew);
                s[qi][kj] = p;
                rs += p;
            }
            #pragma unroll
            for (int o = 8; o > 0; o >>= 1)
                rs += __shfl_xor_sync(0xffffffffu, rs, o, 16);

            l_i[qi] = l_i[qi]*alpha + rs;
            #pragma unroll
            for (int di = 0; di < 4; di++) acc[qi][di] *= alpha;
            #pragma unroll
            for (int kj = 0; kj < 4; kj++)
                Ps[(tx*4+kj)*PITCH + ty*4 + qi] = s[qi][kj];
        }
        __syncthreads();

        #pragma unroll 8
        for (int kk = 0; kk < 64; kk++) {
            const float4 pa = *(const float4*)&Ps[kk*PITCH + ty*4];
            const float4 vb = *(const float4*)&Vs[kk*PITCH + tx*4];
            const float a[4] = {pa.x, pa.y, pa.z, pa.w};
            const float bb[4] = {vb.x, vb.y, vb.z, vb.w};
            #pragma unroll
            for (int qi = 0; qi < 4; qi++)
                #pragma unroll
                for (int di = 0; di < 4; di++)
                    acc[qi][di] = fmaf(a[qi], bb[di], acc[qi][di]);
        }
    }

    #pragma unroll
    for (int qi = 0; qi < 4; qi++) {
        const float inv = 1.0f / l_i[qi];
        float4 v;
        v.x = acc[qi][0]*inv; v.y = acc[qi][1]*inv;
        v.z = acc[qi][2]*inv; v.w = acc[qi][3]*inv;
        *(float4*)&g_attn[(size_t)(b*S_ + q0 + ty*4 + qi)*D_ + h*HD_ + tx*4] = v;
    }
}

// ---------------------------------------------------------------------------
extern "C" void kernel_launch(void* const* d_in, const int* in_sizes, int n_in,
                              void* d_out, int out_size)
{
    const float* x  = (const float*)d_in[0];
    const int*   Mm = (const int*)  d_in[1];
    const float* Wq = (const float*)d_in[2];
    const float* Wk = (const float*)d_in[3];
    const float* Wv = (const float*)d_in[4];
    const float* Wo = (const float*)d_in[5];
    const float* bo = (const float*)d_in[6];
    float* out = (float*)d_out;

    float* attnPtr = nullptr;
    cudaGetSymbolAddress((void**)&attnPtr, g_attn);
    __nv_bfloat16 *xhiPtr = nullptr, *xloPtr = nullptr;
    cudaGetSymbolAddress((void**)&xhiPtr, g_xhi);
    cudaGetSymbolAddress((void**)&xloPtr, g_xlo);

    const int gemm_smem = 2 * 4 * TILE_ELT * 2;   // 81920 B
    cudaFuncSetAttribute(tgemm_kernel<0>,
                         cudaFuncAttributeMaxDynamicSharedMemorySize, gemm_smem);
    cudaFuncSetAttribute(tgemm_kernel<1>,
                         cudaFuncAttributeMaxDynamicSharedMemorySize, gemm_smem);
    const int attn_smem = 4 * 64 * PITCH * (int)sizeof(float);
    cudaFuncSetAttribute(attn_kernel,
                         cudaFuncAttributeMaxDynamicSharedMemorySize, attn_smem);

    // 1) split x and weights to hi/lo bf16
    split_x_kernel<<<NELEM/1024, 256>>>(x, xhiPtr, xloPtr);
    split_w_kernel<<<dim3((D_*D_)/1024, 4), 256>>>(Wq, Wk, Wv, Wo);
    // 2) QKV projections on HMMA tensor cores (z = 0,1,2)
    tgemm_kernel<0><<<dim3(8, 32, 3), 256, gemm_smem>>>(xhiPtr, xloPtr, nullptr, nullptr);
    // 3) masked flash attention -> g_attn [B,S,D]
    attn_kernel<<<dim3(S_/64, B_*H_), 256, attn_smem>>>(Mm);
    // 4) split attention output, then output projection + bias
    split_x_kernel<<<NELEM/1024, 256>>>(attnPtr, xhiPtr, xloPtr);
    tgemm_kernel<1><<<dim3(8, 32, 1), 256, gemm_smem>>>(xhiPtr, xloPtr, bo, out);
}

// round 5
// speedup vs baseline: 2.7460x; 2.0365x over previous
#include <cuda_runtime.h>
#include <cuda_bf16.h>
#include <cstdint>

#define B_  2
#define S_  2048
#define D_  1024
#define H_  16
#define HD_ 64
#define NELEM (B_*S_*D_)      // 4194304

// Scratch (allocation-free rule: __device__ globals)
__device__ __align__(16) float g_V[NELEM];                // [B,H,S,HD] fp32
__device__ __align__(16) __nv_bfloat16 g_xhi[NELEM];      // activations hi
__device__ __align__(16) __nv_bfloat16 g_xlo[NELEM];      // activations lo
__device__ __align__(16) __nv_bfloat16 g_whi[4*D_*D_];    // Wq,Wk,Wv,Wo hi
__device__ __align__(16) __nv_bfloat16 g_wlo[4*D_*D_];    // Wq,Wk,Wv,Wo lo
__device__ __align__(16) __nv_bfloat16 g_Qhi[NELEM];      // [B,H,S,HD] (scaled)
__device__ __align__(16) __nv_bfloat16 g_Qlo[NELEM];
__device__ __align__(16) __nv_bfloat16 g_Khi[NELEM];      // [B,H,S,HD]
__device__ __align__(16) __nv_bfloat16 g_Klo[NELEM];
__device__ __align__(16) __nv_bfloat16 g_Vthi[NELEM];     // [B,H,HD,S] (transposed)
__device__ __align__(16) __nv_bfloat16 g_Vtlo[NELEM];
__device__ __align__(16) uint32_t g_mbits[B_*S_*(S_/32)]; // packed mask bits

// ===========================================================================
// PTX helpers (baseline PTX only — compiles under compute_103)
// ===========================================================================
__device__ __forceinline__ uint32_t smem_u32(const void* p) {
    uint32_t a;
    asm("{ .reg .u64 t; cvta.to.shared.u64 t, %1; cvt.u32.u64 %0, t; }"
        : "=r"(a) : "l"(p));
    return a;
}
__device__ __forceinline__ void cp16(uint32_t saddr, const void* g) {
    asm volatile("cp.async.cg.shared.global [%0], [%1], 16;"
                 :: "r"(saddr), "l"(g) : "memory");
}
__device__ __forceinline__ void ldm_x4(uint32_t* r, uint32_t addr) {
    asm volatile("ldmatrix.sync.aligned.m8n8.x4.shared.b16 {%0,%1,%2,%3}, [%4];"
        : "=r"(r[0]), "=r"(r[1]), "=r"(r[2]), "=r"(r[3]) : "r"(addr));
}
__device__ __forceinline__ void ldm_x2(uint32_t* r, uint32_t addr) {
    asm volatile("ldmatrix.sync.aligned.m8n8.x2.shared.b16 {%0,%1}, [%2];"
        : "=r"(r[0]), "=r"(r[1]) : "r"(addr));
}
__device__ __forceinline__ void mma_bf16(float* c, const uint32_t* a, const uint32_t* b) {
    asm volatile("mma.sync.aligned.m16n8k16.row.col.f32.bf16.bf16.f32 "
        "{%0,%1,%2,%3}, {%4,%5,%6,%7}, {%8,%9}, {%0,%1,%2,%3};"
        : "+f"(c[0]), "+f"(c[1]), "+f"(c[2]), "+f"(c[3])
        : "r"(a[0]), "r"(a[1]), "r"(a[2]), "r"(a[3]), "r"(b[0]), "r"(b[1]));
}

// fp32 pair -> packed hi word + packed lo word (bf16x2 each)
__device__ __forceinline__ void split2(float x, float y, uint32_t& h, uint32_t& l) {
    __nv_bfloat16 hx = __float2bfloat16(x);
    __nv_bfloat16 hy = __float2bfloat16(y);
    __nv_bfloat16 lx = __float2bfloat16(x - __bfloat162float(hx));
    __nv_bfloat16 ly = __float2bfloat16(y - __bfloat162float(hy));
    h = (uint32_t)__bfloat16_as_ushort(hx) | ((uint32_t)__bfloat16_as_ushort(hy) << 16);
    l = (uint32_t)__bfloat16_as_ushort(lx) | ((uint32_t)__bfloat16_as_ushort(ly) << 16);
}

// ---------------------------------------------------------------------------
// split kernels
// ---------------------------------------------------------------------------
__global__ __launch_bounds__(256) void split_x_kernel(
    const float* __restrict__ src,
    __nv_bfloat16* __restrict__ hi, __nv_bfloat16* __restrict__ lo)
{
    const int i = (blockIdx.x * 256 + threadIdx.x) * 4;
    const float4 v = *(const float4*)(src + i);
    uint2 hv, lv;
    split2(v.x, v.y, hv.x, lv.x);
    split2(v.z, v.w, hv.y, lv.y);
    *(uint2*)(hi + i) = hv;
    *(uint2*)(lo + i) = lv;
}

__global__ __launch_bounds__(256) void split_w_kernel(
    const float* __restrict__ w0, const float* __restrict__ w1,
    const float* __restrict__ w2, const float* __restrict__ w3)
{
    const int wsel = blockIdx.y;
    const float* src = (wsel == 0) ? w0 : (wsel == 1) ? w1 : (wsel == 2) ? w2 : w3;
    const int i = (blockIdx.x * 256 + threadIdx.x) * 4;
    const float4 v = *(const float4*)(src + i);
    uint2 hv, lv;
    split2(v.x, v.y, hv.x, lv.x);
    split2(v.z, v.w, hv.y, lv.y);
    const size_t o = (size_t)wsel * D_ * D_ + i;
    *(uint2*)(g_whi + o) = hv;
    *(uint2*)(g_wlo + o) = lv;
}

// ---------------------------------------------------------------------------
// mask pack: bit j of word w of row (b,q) = (M[b,q,w*32+j] != 0)
// ---------------------------------------------------------------------------
__global__ __launch_bounds__(256) void packmask_kernel(const int* __restrict__ M)
{
    const int lane = threadIdx.x & 31;
    const int row = blockIdx.x * 8 + (threadIdx.x >> 5);   // 0..4095
    const int* src = M + (size_t)row * S_;
    uint32_t* dst = g_mbits + row * (S_/32);
    for (int w = 0; w < S_/32; w++) {
        const int v = src[w * 32 + lane];
        const uint32_t bits = __ballot_sync(0xffffffffu, v != 0);
        if (lane == 0) dst[w] = bits;
    }
}

// ---------------------------------------------------------------------------
// V transpose+split: g_V [B,H,S,64] fp32 -> g_Vthi/lo [B,H,64,S] bf16
// ---------------------------------------------------------------------------
__global__ __launch_bounds__(256) void vtrans_kernel()
{
    __shared__ float t[64][65];
    const int bh = blockIdx.y;
    const int k0 = blockIdx.x * 64;
    const float* src = g_V + ((size_t)bh * S_ + k0) * HD_;
    const int tid = threadIdx.x;
    #pragma unroll
    for (int it = 0; it < 4; it++) {
        const int r = (tid >> 4) + it * 16;
        const int c = (tid & 15) * 4;
        const float4 v = *(const float4*)(src + r * HD_ + c);
        t[r][c] = v.x; t[r][c+1] = v.y; t[r][c+2] = v.z; t[r][c+3] = v.w;
    }
    __syncthreads();
    #pragma unroll
    for (int it = 0; it < 4; it++) {
        const int d  = (tid >> 4) + it * 16;
        const int k4 = (tid & 15) * 4;
        uint32_t h0, l0, h1, l1;
        split2(t[k4][d],   t[k4+1][d], h0, l0);
        split2(t[k4+2][d], t[k4+3][d], h1, l1);
        const size_t o = ((size_t)bh * HD_ + d) * S_ + k0 + k4;
        *(uint2*)&g_Vthi[o] = make_uint2(h0, h1);
        *(uint2*)&g_Vtlo[o] = make_uint2(l0, l1);
    }
}

// ===========================================================================
// HMMA GEMM (validated in R4): C[m,n] = sum_k A[m,k]*W[n,k], 3-term bf16.
// MODE 0: z=0 -> Q (scaled, split to g_Qhi/lo), z=1 -> K (split), z=2 -> g_V fp32
// MODE 1: W = Wo (idx 3); out = A@Wo^T + bias -> Cout
// ===========================================================================
#define KC 32
#define NCH 32
#define AP 40
#define TILE_ELT (128*AP)

template<int MODE>
__global__ __launch_bounds__(256) void tgemm_kernel(
    const __nv_bfloat16* __restrict__ Ahi_g,
    const __nv_bfloat16* __restrict__ Alo_g,
    const float* __restrict__ bias,
    float* __restrict__ Cout)
{
    extern __shared__ __nv_bfloat16 smem[];
    const uint32_t sb = smem_u32(smem);

    const int tid = threadIdx.x;
    const int wid = tid >> 5, lane = tid & 31;
    const int m0 = blockIdx.y * 128;
    const int n0 = blockIdx.x * 128;
    const int widx = (MODE == 0) ? blockIdx.z : 3;
    const __nv_bfloat16* Bhi_g = g_whi + (size_t)widx * D_ * D_;
    const __nv_bfloat16* Blo_g = g_wlo + (size_t)widx * D_ * D_;

    const int lrow0 = tid >> 2;
    const int lcol  = (tid & 3) * 8;

    const int arow  = (lane & 7) + ((lane >> 3) & 1) * 8;
    const int akoff = ((lane >> 4) & 1) * 8;
    const int brow  = lane & 7;
    const int bkoff = ((lane >> 3) & 1) * 8;
    const int wm = (wid & 1) * 64;
    const int wn = (wid >> 1) * 32;

    float acc[4][4][4];
    #pragma unroll
    for (int mt = 0; mt < 4; mt++)
        #pragma unroll
        for (int nt = 0; nt < 4; nt++)
            #pragma unroll
            for (int j = 0; j < 4; j++) acc[mt][nt][j] = 0.f;

    auto prefetch = [&](int c) {
        const int buf = c & 1;
        const int kc = c * KC;
        const uint32_t s0 = sb + (uint32_t)(buf * 4 * TILE_ELT) * 2;
        const uint32_t soff = (uint32_t)(lrow0 * AP + lcol) * 2;
        {
            const __nv_bfloat16* g = Ahi_g + (size_t)(m0 + lrow0) * 1024 + kc + lcol;
            cp16(s0 + 0 * TILE_ELT * 2 + soff, g);
            cp16(s0 + 0 * TILE_ELT * 2 + soff + 64 * AP * 2, g + 64 * 1024);
        }
        {
            const __nv_bfloat16* g = Alo_g + (size_t)(m0 + lrow0) * 1024 + kc + lcol;
            cp16(s0 + 1 * TILE_ELT * 2 + soff, g);
            cp16(s0 + 1 * TILE_ELT * 2 + soff + 64 * AP * 2, g + 64 * 1024);
        }
        {
            const __nv_bfloat16* g = Bhi_g + (size_t)(n0 + lrow0) * 1024 + kc + lcol;
            cp16(s0 + 2 * TILE_ELT * 2 + soff, g);
            cp16(s0 + 2 * TILE_ELT * 2 + soff + 64 * AP * 2, g + 64 * 1024);
        }
        {
            const __nv_bfloat16* g = Blo_g + (size_t)(n0 + lrow0) * 1024 + kc + lcol;
            cp16(s0 + 3 * TILE_ELT * 2 + soff, g);
            cp16(s0 + 3 * TILE_ELT * 2 + soff + 64 * AP * 2, g + 64 * 1024);
        }
        asm volatile("cp.async.commit_group;" ::: "memory");
    };

    prefetch(0);

    for (int c = 0; c < NCH; c++) {
        if (c + 1 < NCH) {
            prefetch(c + 1);
            asm volatile("cp.async.wait_group 1;" ::: "memory");
        } else {
            asm volatile("cp.async.wait_group 0;" ::: "memory");
        }
        __syncthreads();

        const int buf = c & 1;
        const uint32_t base = sb + (uint32_t)(buf * 4 * TILE_ELT) * 2;
        const uint32_t aAhi = base;
        const uint32_t aAlo = base + (uint32_t)TILE_ELT * 2;
        const uint32_t aBhi = base + (uint32_t)TILE_ELT * 4;
        const uint32_t aBlo = base + (uint32_t)TILE_ELT * 6;

        #pragma unroll
        for (int ks = 0; ks < 2; ks++) {
            const int k0 = ks * 16;
            uint32_t bh[4][2], bl[4][2];
            #pragma unroll
            for (int nt = 0; nt < 4; nt++) {
                const uint32_t ba =
                    (uint32_t)((wn + nt * 8 + brow) * AP + k0 + bkoff) * 2;
                ldm_x2(bh[nt], aBhi + ba);
                ldm_x2(bl[nt], aBlo + ba);
            }
            #pragma unroll
            for (int mt = 0; mt < 4; mt++) {
                const uint32_t aa =
                    (uint32_t)((wm + mt * 16 + arow) * AP + k0 + akoff) * 2;
                uint32_t ah[4], al[4];
                ldm_x4(ah, aAhi + aa);
                ldm_x4(al, aAlo + aa);
                #pragma unroll
                for (int nt = 0; nt < 4; nt++) {
                    mma_bf16(acc[mt][nt], ah, bh[nt]);
                    mma_bf16(acc[mt][nt], ah, bl[nt]);
                    mma_bf16(acc[mt][nt], al, bh[nt]);
                }
            }
        }
        __syncthreads();
    }

    // ---- epilogue ----
    const int r_lo  = lane >> 2;
    const int coff  = (lane & 3) * 2;
    const float scale = (MODE == 0 && blockIdx.z == 0) ? 0.125f : 1.0f;

    #pragma unroll
    for (int mt = 0; mt < 4; mt++) {
        const int r0 = m0 + wm + mt * 16 + r_lo;
        const int r1 = r0 + 8;
        #pragma unroll
        for (int nt = 0; nt < 4; nt++) {
            const int cg = n0 + wn + nt * 8 + coff;
            float2 v0 = make_float2(acc[mt][nt][0] * scale, acc[mt][nt][1] * scale);
            float2 v1 = make_float2(acc[mt][nt][2] * scale, acc[mt][nt][3] * scale);
            if (MODE == 0) {
                const int h = cg >> 6, hd = cg & 63;
                #pragma unroll
                for (int half = 0; half < 2; half++) {
                    const int rr = half ? r1 : r0;
                    const float2 v = half ? v1 : v0;
                    const int bb_ = rr >> 11, ss = rr & 2047;
                    const size_t o = (((size_t)(bb_ * H_ + h)) * S_ + ss) * HD_ + hd;
                    if (blockIdx.z == 2) {
                        *(float2*)&g_V[o] = v;
                    } else {
                        uint32_t hw, lw;
                        split2(v.x, v.y, hw, lw);
                        if (blockIdx.z == 0) {
                            *(uint32_t*)&g_Qhi[o] = hw;
                            *(uint32_t*)&g_Qlo[o] = lw;
                        } else {
                            *(uint32_t*)&g_Khi[o] = hw;
                            *(uint32_t*)&g_Klo[o] = lw;
                        }
                    }
                }
            } else {
                const float2 bb = *(const float2*)&bias[cg];
                v0.x += bb.x; v0.y += bb.y;
                v1.x += bb.x; v1.y += bb.y;
                *(float2*)&Cout[(size_t)r0 * 1024 + cg] = v0;
                *(float2*)&Cout[(size_t)r1 * 1024 + cg] = v1;
            }
        }
    }
}

// ===========================================================================
// Tensor-core flash attention.
// Block = 128 queries x one (b,h). 8 warps, warp = 16 q rows x 64 keys/dims.
// 64-key chunks x 32, cp.async double buffer. Q/K/Vt in bf16 hi/lo (pitch 72).
// Output written as bf16 hi/lo directly into g_xhi/g_xlo [B,S,D].
// ===========================================================================
#define QP 72
#define QSZ (128*QP)
#define CHE (64*QP)

__global__ __launch_bounds__(256) void attn_tc()
{
    extern __shared__ __nv_bfloat16 sm[];
    const uint32_t sb = smem_u32(sm);
    const int tid = threadIdx.x, wid = tid >> 5, lane = tid & 31;
    const int bh = blockIdx.y, b = bh >> 4, h = bh & 15;
    const int q0 = blockIdx.x * 128;

    const __nv_bfloat16* Qhi_g = g_Qhi + ((size_t)bh * S_ + q0) * HD_;
    const __nv_bfloat16* Qlo_g = g_Qlo + ((size_t)bh * S_ + q0) * HD_;
    const __nv_bfloat16* Khi_g = g_Khi + (size_t)bh * S_ * HD_;
    const __nv_bfloat16* Klo_g = g_Klo + (size_t)bh * S_ * HD_;
    const __nv_bfloat16* Vhi_g = g_Vthi + (size_t)bh * HD_ * S_;
    const __nv_bfloat16* Vlo_g = g_Vtlo + (size_t)bh * HD_ * S_;

    // Q tile -> smem (hi, lo), once; joins cp.async group 0
    #pragma unroll
    for (int t = 0; t < 8; t++) {
        const int i = tid + t * 256;
        const int mat = i >> 10, rem = i & 1023, row = rem >> 3, c16 = rem & 7;
        const __nv_bfloat16* g = (mat ? Qlo_g : Qhi_g) + row * HD_ + c16 * 8;
        cp16(sb + (uint32_t)(mat * QSZ + row * QP) * 2 + c16 * 16, g);
    }

    auto prefetch = [&](int c) {
        const int buf = c & 1;
        const int k0 = c * 64;
        const uint32_t base = (uint32_t)(2 * QSZ + buf * 4 * CHE);
        #pragma unroll
        for (int t = 0; t < 8; t++) {
            const int i = tid + t * 256;
            const int mat = i >> 9, rem = i & 511, row = rem >> 3, c16 = rem & 7;
            const __nv_bfloat16* g;
            if (mat == 0)      g = Khi_g + (size_t)(k0 + row) * HD_ + c16 * 8;
            else if (mat == 1) g = Klo_g + (size_t)(k0 + row) * HD_ + c16 * 8;
            else if (mat == 2) g = Vhi_g + (size_t)row * S_ + k0 + c16 * 8;
            else               g = Vlo_g + (size_t)row * S_ + k0 + c16 * 8;
            cp16(sb + (base + (uint32_t)(mat * CHE + row * QP)) * 2 + c16 * 16, g);
        }
        asm volatile("cp.async.commit_group;" ::: "memory");
    };

    prefetch(0);

    const int arow  = (lane & 7) + ((lane >> 3) & 1) * 8;
    const int akoff = ((lane >> 4) & 1) * 8;
    const int brow  = lane & 7;
    const int bkoff = ((lane >> 3) & 1) * 8;
    const int r = lane >> 2;

    float out[8][4];
    #pragma unroll
    for (int nt = 0; nt < 8; nt++)
        #pragma unroll
        for (int j = 0; j < 4; j++) out[nt][j] = 0.f;
    float m0 = -1e30f, m1 = -1e30f, l0 = 0.f, l1 = 0.f;

    const uint32_t mrow0 = ((uint32_t)b * S_ + q0 + wid * 16 + r) * (S_/32);

    for (int c = 0; c < 32; c++) {
        if (c + 1 < 32) {
            prefetch(c + 1);
            asm volatile("cp.async.wait_group 1;" ::: "memory");
        } else {
            asm volatile("cp.async.wait_group 0;" ::: "memory");
        }
        __syncthreads();

        const int buf = c & 1;
        const uint32_t kb = (uint32_t)(2 * QSZ + buf * 4 * CHE);

        // ---- S = Q K^T ----
        float s[8][4];
        #pragma unroll
        for (int nt = 0; nt < 8; nt++)
            #pragma unroll
            for (int j = 0; j < 4; j++) s[nt][j] = 0.f;

        #pragma unroll
        for (int ks = 0; ks < 4; ks++) {
            uint32_t qh[4], ql[4];
            const uint32_t qa =
                (uint32_t)((wid * 16 + arow) * QP + ks * 16 + akoff) * 2;
            ldm_x4(qh, sb + qa);
            ldm_x4(ql, sb + (uint32_t)QSZ * 2 + qa);
            #pragma unroll
            for (int nt = 0; nt < 8; nt++) {
                uint32_t kh[2], kl[2];
                const uint32_t ka = sb +
                    (kb + (uint32_t)((nt * 8 + brow) * QP + ks * 16 + bkoff)) * 2;
                ldm_x2(kh, ka);
                ldm_x2(kl, ka + (uint32_t)CHE * 2);
                mma_bf16(s[nt], qh, kh);
                mma_bf16(s[nt], qh, kl);
                mma_bf16(s[nt], ql, kh);
            }
        }

        // ---- mask ----
        const uint32_t widx = (uint32_t)(c * 2);
        const uint2 mw0 = *(const uint2*)(g_mbits + mrow0 + widx);
        const uint2 mw1 = *(const uint2*)(g_mbits + mrow0 + 8 * (S_/32) + widx);
        #pragma unroll
        for (int nt = 0; nt < 8; nt++) {
            const int sh = ((nt * 8) & 31) + (lane & 3) * 2;
            const uint32_t w0 = (nt < 4) ? mw0.x : mw0.y;
            const uint32_t w1 = (nt < 4) ? mw1.x : mw1.y;
            if (!((w0 >> sh) & 1))       s[nt][0] = -1e9f;
            if (!((w0 >> (sh + 1)) & 1)) s[nt][1] = -1e9f;
            if (!((w1 >> sh) & 1))       s[nt][2] = -1e9f;
            if (!((w1 >> (sh + 1)) & 1)) s[nt][3] = -1e9f;
        }

        // ---- online softmax (rows r and r+8) ----
        float mx0 = -1e30f, mx1 = -1e30f;
        #pragma unroll
        for (int nt = 0; nt < 8; nt++) {
            mx0 = fmaxf(mx0, fmaxf(s[nt][0], s[nt][1]));
            mx1 = fmaxf(mx1, fmaxf(s[nt][2], s[nt][3]));
        }
        mx0 = fmaxf(mx0, __shfl_xor_sync(0xffffffffu, mx0, 1));
        mx0 = fmaxf(mx0, __shfl_xor_sync(0xffffffffu, mx0, 2));
        mx1 = fmaxf(mx1, __shfl_xor_sync(0xffffffffu, mx1, 1));
        mx1 = fmaxf(mx1, __shfl_xor_sync(0xffffffffu, mx1, 2));

        const float mn0 = fmaxf(m0, mx0);
        const float mn1 = fmaxf(m1, mx1);
        const float a0 = __expf(m0 - mn0);
        const float a1 = __expf(m1 - mn1);
        m0 = mn0; m1 = mn1;

        float s0 = 0.f, s1 = 0.f;
        #pragma unroll
        for (int nt = 0; nt < 8; nt++) {
            s[nt][0] = __expf(s[nt][0] - mn0); s0 += s[nt][0];
            s[nt][1] = __expf(s[nt][1] - mn0); s0 += s[nt][1];
            s[nt][2] = __expf(s[nt][2] - mn1); s1 += s[nt][2];
            s[nt][3] = __expf(s[nt][3] - mn1); s1 += s[nt][3];
        }
        s0 += __shfl_xor_sync(0xffffffffu, s0, 1);
        s0 += __shfl_xor_sync(0xffffffffu, s0, 2);
        s1 += __shfl_xor_sync(0xffffffffu, s1, 1);
        s1 += __shfl_xor_sync(0xffffffffu, s1, 2);
        l0 = l0 * a0 + s0;
        l1 = l1 * a1 + s1;

        #pragma unroll
        for (int nt = 0; nt < 8; nt++) {
            out[nt][0] *= a0; out[nt][1] *= a0;
            out[nt][2] *= a1; out[nt][3] *= a1;
        }

        // ---- out += P V (P from S fragments, no smem roundtrip) ----
        #pragma unroll
        for (int j = 0; j < 4; j++) {
            uint32_t ah[4], al[4];
            split2(s[2*j][0],   s[2*j][1],   ah[0], al[0]);
            split2(s[2*j][2],   s[2*j][3],   ah[1], al[1]);
            split2(s[2*j+1][0], s[2*j+1][1], ah[2], al[2]);
            split2(s[2*j+1][2], s[2*j+1][3], ah[3], al[3]);
            #pragma unroll
            for (int nt = 0; nt < 8; nt++) {
                uint32_t vh[2], vl[2];
                const uint32_t va = sb +
                    (kb + (uint32_t)(2 * CHE + (nt * 8 + brow) * QP + j * 16 + bkoff)) * 2;
                ldm_x2(vh, va);
                ldm_x2(vl, va + (uint32_t)CHE * 2);
                mma_bf16(out[nt], ah, vh);
                mma_bf16(out[nt], ah, vl);
                mma_bf16(out[nt], al, vh);
            }
        }
        __syncthreads();
    }

    // ---- epilogue: normalize, split, store bf16 hi/lo into g_xhi/g_xlo ----
    const float i0 = 1.0f / l0;
    const float i1 = 1.0f / l1;
    const int qg = q0 + wid * 16 + r;
    #pragma unroll
    for (int nt = 0; nt < 8; nt++) {
        const int d = nt * 8 + (lane & 3) * 2;
        const size_t o0 = ((size_t)b * S_ + qg) * D_ + h * HD_ + d;
        const size_t o1 = o0 + 8 * D_;
        uint32_t hw, lw;
        split2(out[nt][0] * i0, out[nt][1] * i0, hw, lw);
        *(uint32_t*)&g_xhi[o0] = hw;
        *(uint32_t*)&g_xlo[o0] = lw;
        split2(out[nt][2] * i1, out[nt][3] * i1, hw, lw);
        *(uint32_t*)&g_xhi[o1] = hw;
        *(uint32_t*)&g_xlo[o1] = lw;
    }
}

// ---------------------------------------------------------------------------
extern "C" void kernel_launch(void* const* d_in, const int* in_sizes, int n_in,
                              void* d_out, int out_size)
{
    const float* x  = (const float*)d_in[0];
    const int*   Mm = (const int*)  d_in[1];
    const float* Wq = (const float*)d_in[2];
    const float* Wk = (const float*)d_in[3];
    const float* Wv = (const float*)d_in[4];
    const float* Wo = (const float*)d_in[5];
    const float* bo = (const float*)d_in[6];
    float* out = (float*)d_out;

    __nv_bfloat16 *xhiPtr = nullptr, *xloPtr = nullptr;
    cudaGetSymbolAddress((void**)&xhiPtr, g_xhi);
    cudaGetSymbolAddress((void**)&xloPtr, g_xlo);

    const int gemm_smem = 2 * 4 * TILE_ELT * 2;             // 81920 B
    cudaFuncSetAttribute(tgemm_kernel<0>,
                         cudaFuncAttributeMaxDynamicSharedMemorySize, gemm_smem);
    cudaFuncSetAttribute(tgemm_kernel<1>,
                         cudaFuncAttributeMaxDynamicSharedMemorySize, gemm_smem);
    const int attn_smem = (2 * QSZ + 8 * CHE) * 2;          // 110592 B
    cudaFuncSetAttribute(attn_tc,
                         cudaFuncAttributeMaxDynamicSharedMemorySize, attn_smem);

    // 1) split input x and all weights to hi/lo bf16
    split_x_kernel<<<NELEM/1024, 256>>>(x, xhiPtr, xloPtr);
    split_w_kernel<<<dim3((D_*D_)/1024, 4), 256>>>(Wq, Wk, Wv, Wo);
    // 2) QKV projections (HMMA); epilogue splits Q/K to bf16, V stays fp32
    tgemm_kernel<0><<<dim3(8, 32, 3), 256, gemm_smem>>>(xhiPtr, xloPtr, nullptr, nullptr);
    // 3) pack mask bits; transpose+split V
    packmask_kernel<<<(B_*S_)/8, 256>>>(Mm);
    vtrans_kernel<<<dim3(S_/64, B_*H_), 256>>>();
    // 4) tensor-core flash attention -> g_xhi/g_xlo [B,S,D]
    attn_tc<<<dim3(S_/128, B_*H_), 256, attn_smem>>>();
    // 5) output projection + bias (HMMA)
    tgemm_kernel<1><<<dim3(8, 32, 1), 256, gemm_smem>>>(xhiPtr, xloPtr, bo, out);
}

// round 6
// speedup vs baseline: 2.8328x; 1.0316x over previous
#include <cuda_runtime.h>
#include <cuda_bf16.h>
#include <cstdint>

#define B_  2
#define S_  2048
#define D_  1024
#define H_  16
#define HD_ 64
#define NELEM (B_*S_*D_)      // 4194304

// Scratch (allocation-free rule: __device__ globals)
__device__ __align__(16) float g_V[NELEM];                // [B,H,S,HD] fp32
__device__ __align__(16) __nv_bfloat16 g_xhi[NELEM];      // activations hi
__device__ __align__(16) __nv_bfloat16 g_xlo[NELEM];      // activations lo
__device__ __align__(16) __nv_bfloat16 g_whi[4*D_*D_];    // Wq,Wk,Wv,Wo hi
__device__ __align__(16) __nv_bfloat16 g_wlo[4*D_*D_];    // Wq,Wk,Wv,Wo lo
__device__ __align__(16) __nv_bfloat16 g_Qhi[NELEM];      // [B,H,S,HD] (scaled by 0.125*log2e)
__device__ __align__(16) __nv_bfloat16 g_Qlo[NELEM];
__device__ __align__(16) __nv_bfloat16 g_Khi[NELEM];      // [B,H,S,HD]
__device__ __align__(16) __nv_bfloat16 g_Klo[NELEM];
__device__ __align__(16) __nv_bfloat16 g_Vthi[NELEM];     // [B,H,HD,S] (transposed)
__device__ __align__(16) __nv_bfloat16 g_Vtlo[NELEM];
__device__ __align__(16) uint32_t g_mbits[B_*S_*(S_/32)]; // packed mask bits

// ===========================================================================
// PTX helpers (baseline PTX only — compiles under compute_103)
// ===========================================================================
__device__ __forceinline__ uint32_t smem_u32(const void* p) {
    uint32_t a;
    asm("{ .reg .u64 t; cvta.to.shared.u64 t, %1; cvt.u32.u64 %0, t; }"
        : "=r"(a) : "l"(p));
    return a;
}
__device__ __forceinline__ void cp16(uint32_t saddr, const void* g) {
    asm volatile("cp.async.cg.shared.global [%0], [%1], 16;"
                 :: "r"(saddr), "l"(g) : "memory");
}
__device__ __forceinline__ void ldm_x4(uint32_t* r, uint32_t addr) {
    asm volatile("ldmatrix.sync.aligned.m8n8.x4.shared.b16 {%0,%1,%2,%3}, [%4];"
        : "=r"(r[0]), "=r"(r[1]), "=r"(r[2]), "=r"(r[3]) : "r"(addr));
}
__device__ __forceinline__ void ldm_x2(uint32_t* r, uint32_t addr) {
    asm volatile("ldmatrix.sync.aligned.m8n8.x2.shared.b16 {%0,%1}, [%2];"
        : "=r"(r[0]), "=r"(r[1]) : "r"(addr));
}
__device__ __forceinline__ void mma_bf16(float* c, const uint32_t* a, const uint32_t* b) {
    asm volatile("mma.sync.aligned.m16n8k16.row.col.f32.bf16.bf16.f32 "
        "{%0,%1,%2,%3}, {%4,%5,%6,%7}, {%8,%9}, {%0,%1,%2,%3};"
        : "+f"(c[0]), "+f"(c[1]), "+f"(c[2]), "+f"(c[3])
        : "r"(a[0]), "r"(a[1]), "r"(a[2]), "r"(a[3]), "r"(b[0]), "r"(b[1]));
}
__device__ __forceinline__ float ex2f(float x) {
    float r;
    asm("ex2.approx.f32 %0, %1;" : "=f"(r) : "f"(x));
    return r;
}

// Fast fp32 pair -> packed hi (truncated bf16) + packed lo (rounded remainder)
__device__ __forceinline__ void split2(float x, float y, uint32_t& h, uint32_t& l) {
    const uint32_t xb = __float_as_uint(x) & 0xFFFF0000u;
    const uint32_t yb = __float_as_uint(y) & 0xFFFF0000u;
    h = (xb >> 16) | yb;                       // {lo16=bf16(x), hi16=bf16(y)}
    const float lx = x - __uint_as_float(xb);  // exact
    const float ly = y - __uint_as_float(yb);  // exact
    asm("cvt.rn.bf16x2.f32 %0, %1, %2;" : "=r"(l) : "f"(ly), "f"(lx));
}

// ---------------------------------------------------------------------------
// split kernels
// ---------------------------------------------------------------------------
__global__ __launch_bounds__(256) void split_x_kernel(
    const float* __restrict__ src,
    __nv_bfloat16* __restrict__ hi, __nv_bfloat16* __restrict__ lo)
{
    const int i = (blockIdx.x * 256 + threadIdx.x) * 4;
    const float4 v = *(const float4*)(src + i);
    uint2 hv, lv;
    split2(v.x, v.y, hv.x, lv.x);
    split2(v.z, v.w, hv.y, lv.y);
    *(uint2*)(hi + i) = hv;
    *(uint2*)(lo + i) = lv;
}

__global__ __launch_bounds__(256) void split_w_kernel(
    const float* __restrict__ w0, const float* __restrict__ w1,
    const float* __restrict__ w2, const float* __restrict__ w3)
{
    const int wsel = blockIdx.y;
    const float* src = (wsel == 0) ? w0 : (wsel == 1) ? w1 : (wsel == 2) ? w2 : w3;
    const int i = (blockIdx.x * 256 + threadIdx.x) * 4;
    const float4 v = *(const float4*)(src + i);
    uint2 hv, lv;
    split2(v.x, v.y, hv.x, lv.x);
    split2(v.z, v.w, hv.y, lv.y);
    const size_t o = (size_t)wsel * D_ * D_ + i;
    *(uint2*)(g_whi + o) = hv;
    *(uint2*)(g_wlo + o) = lv;
}

// ---------------------------------------------------------------------------
// mask pack: bit j of word w of row (b,q) = (M[b,q,w*32+j] != 0)
// ---------------------------------------------------------------------------
__global__ __launch_bounds__(256) void packmask_kernel(const int* __restrict__ M)
{
    const int lane = threadIdx.x & 31;
    const int row = blockIdx.x * 8 + (threadIdx.x >> 5);   // 0..4095
    const int* src = M + (size_t)row * S_;
    uint32_t* dst = g_mbits + row * (S_/32);
    for (int w = 0; w < S_/32; w++) {
        const int v = src[w * 32 + lane];
        const uint32_t bits = __ballot_sync(0xffffffffu, v != 0);
        if (lane == 0) dst[w] = bits;
    }
}

// ---------------------------------------------------------------------------
// V transpose+split: g_V [B,H,S,64] fp32 -> g_Vthi/lo [B,H,64,S] bf16
// ---------------------------------------------------------------------------
__global__ __launch_bounds__(256) void vtrans_kernel()
{
    __shared__ float t[64][65];
    const int bh = blockIdx.y;
    const int k0 = blockIdx.x * 64;
    const float* src = g_V + ((size_t)bh * S_ + k0) * HD_;
    const int tid = threadIdx.x;
    #pragma unroll
    for (int it = 0; it < 4; it++) {
        const int r = (tid >> 4) + it * 16;
        const int c = (tid & 15) * 4;
        const float4 v = *(const float4*)(src + r * HD_ + c);
        t[r][c] = v.x; t[r][c+1] = v.y; t[r][c+2] = v.z; t[r][c+3] = v.w;
    }
    __syncthreads();
    #pragma unroll
    for (int it = 0; it < 4; it++) {
        const int d  = (tid >> 4) + it * 16;
        const int k4 = (tid & 15) * 4;
        uint32_t h0, l0, h1, l1;
        split2(t[k4][d],   t[k4+1][d], h0, l0);
        split2(t[k4+2][d], t[k4+3][d], h1, l1);
        const size_t o = ((size_t)bh * HD_ + d) * S_ + k0 + k4;
        *(uint2*)&g_Vthi[o] = make_uint2(h0, h1);
        *(uint2*)&g_Vtlo[o] = make_uint2(l0, l1);
    }
}

// ===========================================================================
// HMMA GEMM (validated): C[m,n] = sum_k A[m,k]*W[n,k], 3-term bf16.
// MODE 0: z=0 -> Q (scaled by 0.125*log2e, split), z=1 -> K (split), z=2 -> V fp32
// MODE 1: W = Wo (idx 3); out = A@Wo^T + bias -> Cout
// ===========================================================================
#define KC 32
#define NCH 32
#define AP 40
#define TILE_ELT (128*AP)

template<int MODE>
__global__ __launch_bounds__(256) void tgemm_kernel(
    const __nv_bfloat16* __restrict__ Ahi_g,
    const __nv_bfloat16* __restrict__ Alo_g,
    const float* __restrict__ bias,
    float* __restrict__ Cout)
{
    extern __shared__ __nv_bfloat16 smem[];
    const uint32_t sb = smem_u32(smem);

    const int tid = threadIdx.x;
    const int wid = tid >> 5, lane = tid & 31;
    const int m0 = blockIdx.y * 128;
    const int n0 = blockIdx.x * 128;
    const int widx = (MODE == 0) ? blockIdx.z : 3;
    const __nv_bfloat16* Bhi_g = g_whi + (size_t)widx * D_ * D_;
    const __nv_bfloat16* Blo_g = g_wlo + (size_t)widx * D_ * D_;

    const int lrow0 = tid >> 2;
    const int lcol  = (tid & 3) * 8;

    const int arow  = (lane & 7) + ((lane >> 3) & 1) * 8;
    const int akoff = ((lane >> 4) & 1) * 8;
    const int brow  = lane & 7;
    const int bkoff = ((lane >> 3) & 1) * 8;
    const int wm = (wid & 1) * 64;
    const int wn = (wid >> 1) * 32;

    float acc[4][4][4];
    #pragma unroll
    for (int mt = 0; mt < 4; mt++)
        #pragma unroll
        for (int nt = 0; nt < 4; nt++)
            #pragma unroll
            for (int j = 0; j < 4; j++) acc[mt][nt][j] = 0.f;

    auto prefetch = [&](int c) {
        const int buf = c & 1;
        const int kc = c * KC;
        const uint32_t s0 = sb + (uint32_t)(buf * 4 * TILE_ELT) * 2;
        const uint32_t soff = (uint32_t)(lrow0 * AP + lcol) * 2;
        {
            const __nv_bfloat16* g = Ahi_g + (size_t)(m0 + lrow0) * 1024 + kc + lcol;
            cp16(s0 + 0 * TILE_ELT * 2 + soff, g);
            cp16(s0 + 0 * TILE_ELT * 2 + soff + 64 * AP * 2, g + 64 * 1024);
        }
        {
            const __nv_bfloat16* g = Alo_g + (size_t)(m0 + lrow0) * 1024 + kc + lcol;
            cp16(s0 + 1 * TILE_ELT * 2 + soff, g);
            cp16(s0 + 1 * TILE_ELT * 2 + soff + 64 * AP * 2, g + 64 * 1024);
        }
        {
            const __nv_bfloat16* g = Bhi_g + (size_t)(n0 + lrow0) * 1024 + kc + lcol;
            cp16(s0 + 2 * TILE_ELT * 2 + soff, g);
            cp16(s0 + 2 * TILE_ELT * 2 + soff + 64 * AP * 2, g + 64 * 1024);
        }
        {
            const __nv_bfloat16* g = Blo_g + (size_t)(n0 + lrow0) * 1024 + kc + lcol;
            cp16(s0 + 3 * TILE_ELT * 2 + soff, g);
            cp16(s0 + 3 * TILE_ELT * 2 + soff + 64 * AP * 2, g + 64 * 1024);
        }
        asm volatile("cp.async.commit_group;" ::: "memory");
    };

    prefetch(0);

    for (int c = 0; c < NCH; c++) {
        if (c + 1 < NCH) {
            prefetch(c + 1);
            asm volatile("cp.async.wait_group 1;" ::: "memory");
        } else {
            asm volatile("cp.async.wait_group 0;" ::: "memory");
        }
        __syncthreads();

        const int buf = c & 1;
        const uint32_t base = sb + (uint32_t)(buf * 4 * TILE_ELT) * 2;
        const uint32_t aAhi = base;
        const uint32_t aAlo = base + (uint32_t)TILE_ELT * 2;
        const uint32_t aBhi = base + (uint32_t)TILE_ELT * 4;
        const uint32_t aBlo = base + (uint32_t)TILE_ELT * 6;

        #pragma unroll
        for (int ks = 0; ks < 2; ks++) {
            const int k0 = ks * 16;
            uint32_t bh[4][2], bl[4][2];
            #pragma unroll
            for (int nt = 0; nt < 4; nt++) {
                const uint32_t ba =
                    (uint32_t)((wn + nt * 8 + brow) * AP + k0 + bkoff) * 2;
                ldm_x2(bh[nt], aBhi + ba);
                ldm_x2(bl[nt], aBlo + ba);
            }
            #pragma unroll
            for (int mt = 0; mt < 4; mt++) {
                const uint32_t aa =
                    (uint32_t)((wm + mt * 16 + arow) * AP + k0 + akoff) * 2;
                uint32_t ah[4], al[4];
                ldm_x4(ah, aAhi + aa);
                ldm_x4(al, aAlo + aa);
                #pragma unroll
                for (int nt = 0; nt < 4; nt++) {
                    mma_bf16(acc[mt][nt], ah, bh[nt]);
                    mma_bf16(acc[mt][nt], ah, bl[nt]);
                    mma_bf16(acc[mt][nt], al, bh[nt]);
                }
            }
        }
        __syncthreads();
    }

    // ---- epilogue ----
    const int r_lo  = lane >> 2;
    const int coff  = (lane & 3) * 2;
    // Q scale folds softmax 1/sqrt(64) AND log2(e) for exp2-based softmax
    const float scale = (MODE == 0 && blockIdx.z == 0) ? 0.125f * 1.44269504f : 1.0f;

    #pragma unroll
    for (int mt = 0; mt < 4; mt++) {
        const int r0 = m0 + wm + mt * 16 + r_lo;
        const int r1 = r0 + 8;
        #pragma unroll
        for (int nt = 0; nt < 4; nt++) {
            const int cg = n0 + wn + nt * 8 + coff;
            float2 v0 = make_float2(acc[mt][nt][0] * scale, acc[mt][nt][1] * scale);
            float2 v1 = make_float2(acc[mt][nt][2] * scale, acc[mt][nt][3] * scale);
            if (MODE == 0) {
                const int h = cg >> 6, hd = cg & 63;
                #pragma unroll
                for (int half = 0; half < 2; half++) {
                    const int rr = half ? r1 : r0;
                    const float2 v = half ? v1 : v0;
                    const int bb_ = rr >> 11, ss = rr & 2047;
                    const size_t o = (((size_t)(bb_ * H_ + h)) * S_ + ss) * HD_ + hd;
                    if (blockIdx.z == 2) {
                        *(float2*)&g_V[o] = v;
                    } else {
                        uint32_t hw, lw;
                        split2(v.x, v.y, hw, lw);
                        if (blockIdx.z == 0) {
                            *(uint32_t*)&g_Qhi[o] = hw;
                            *(uint32_t*)&g_Qlo[o] = lw;
                        } else {
                            *(uint32_t*)&g_Khi[o] = hw;
                            *(uint32_t*)&g_Klo[o] = lw;
                        }
                    }
                }
            } else {
                const float2 bb = *(const float2*)&bias[cg];
                v0.x += bb.x; v0.y += bb.y;
                v1.x += bb.x; v1.y += bb.y;
                *(float2*)&Cout[(size_t)r0 * 1024 + cg] = v0;
                *(float2*)&Cout[(size_t)r1 * 1024 + cg] = v1;
            }
        }
    }
}

// ===========================================================================
// Tensor-core flash attention, 512 threads / 256 queries per CTA.
// 16 warps, warp = 16 q rows x 64 keys/dims. 64-key chunks x 32, cp.async
// double buffer. Q/K/Vt bf16 hi/lo (pitch 72). exp2-domain softmax.
// Output written as bf16 hi/lo directly into g_xhi/g_xlo [B,S,D].
// ===========================================================================
#define QP 72
#define QROWS 256
#define QSZ (QROWS*QP)
#define CHE (64*QP)

__global__ __launch_bounds__(512) void attn_tc()
{
    extern __shared__ __nv_bfloat16 sm[];
    const uint32_t sb = smem_u32(sm);
    const int tid = threadIdx.x, wid = tid >> 5, lane = tid & 31;
    const int bh = blockIdx.y, b = bh >> 4, h = bh & 15;
    const int q0 = blockIdx.x * QROWS;

    const __nv_bfloat16* Qhi_g = g_Qhi + ((size_t)bh * S_ + q0) * HD_;
    const __nv_bfloat16* Qlo_g = g_Qlo + ((size_t)bh * S_ + q0) * HD_;
    const __nv_bfloat16* Khi_g = g_Khi + (size_t)bh * S_ * HD_;
    const __nv_bfloat16* Klo_g = g_Klo + (size_t)bh * S_ * HD_;
    const __nv_bfloat16* Vhi_g = g_Vthi + (size_t)bh * HD_ * S_;
    const __nv_bfloat16* Vlo_g = g_Vtlo + (size_t)bh * HD_ * S_;

    // Q tiles (hi, lo) -> smem once; joins cp.async group 0
    #pragma unroll
    for (int t = 0; t < 8; t++) {
        const int i = tid + t * 512;                 // 0..4095
        const int mat = i >> 11, rem = i & 2047, row = rem >> 3, c16 = rem & 7;
        const __nv_bfloat16* g = (mat ? Qlo_g : Qhi_g) + row * HD_ + c16 * 8;
        cp16(sb + (uint32_t)(mat * QSZ + row * QP) * 2 + c16 * 16, g);
    }

    auto prefetch = [&](int c) {
        const int buf = c & 1;
        const int k0 = c * 64;
        const uint32_t base = (uint32_t)(2 * QSZ + buf * 4 * CHE);
        #pragma unroll
        for (int t = 0; t < 4; t++) {
            const int i = tid + t * 512;             // 0..2047
            const int mat = i >> 9, rem = i & 511, row = rem >> 3, c16 = rem & 7;
            const __nv_bfloat16* g;
            if (mat == 0)      g = Khi_g + (size_t)(k0 + row) * HD_ + c16 * 8;
            else if (mat == 1) g = Klo_g + (size_t)(k0 + row) * HD_ + c16 * 8;
            else if (mat == 2) g = Vhi_g + (size_t)row * S_ + k0 + c16 * 8;
            else               g = Vlo_g + (size_t)row * S_ + k0 + c16 * 8;
            cp16(sb + (base + (uint32_t)(mat * CHE + row * QP)) * 2 + c16 * 16, g);
        }
        asm volatile("cp.async.commit_group;" ::: "memory");
    };

    prefetch(0);

    const int arow  = (lane & 7) + ((lane >> 3) & 1) * 8;
    const int akoff = ((lane >> 4) & 1) * 8;
    const int brow  = lane & 7;
    const int bkoff = ((lane >> 3) & 1) * 8;
    const int r = lane >> 2;

    float out[8][4];
    #pragma unroll
    for (int nt = 0; nt < 8; nt++)
        #pragma unroll
        for (int j = 0; j < 4; j++) out[nt][j] = 0.f;
    float m0 = -1e30f, m1 = -1e30f, l0 = 0.f, l1 = 0.f;

    const uint32_t mrow0 = ((uint32_t)b * S_ + q0 + wid * 16 + r) * (S_/32);

    for (int c = 0; c < 32; c++) {
        if (c + 1 < 32) {
            prefetch(c + 1);
            asm volatile("cp.async.wait_group 1;" ::: "memory");
        } else {
            asm volatile("cp.async.wait_group 0;" ::: "memory");
        }
        __syncthreads();

        const int buf = c & 1;
        const uint32_t kb = (uint32_t)(2 * QSZ + buf * 4 * CHE);

        // ---- S = Q K^T (already in log2e domain via Q scale) ----
        float s[8][4];
        #pragma unroll
        for (int nt = 0; nt < 8; nt++)
            #pragma unroll
            for (int j = 0; j < 4; j++) s[nt][j] = 0.f;

        #pragma unroll
        for (int ks = 0; ks < 4; ks++) {
            uint32_t qh[4], ql[4];
            const uint32_t qa =
                (uint32_t)((wid * 16 + arow) * QP + ks * 16 + akoff) * 2;
            ldm_x4(qh, sb + qa);
            ldm_x4(ql, sb + (uint32_t)QSZ * 2 + qa);
            #pragma unroll
            for (int nt = 0; nt < 8; nt++) {
                uint32_t kh[2], kl[2];
                const uint32_t ka = sb +
                    (kb + (uint32_t)((nt * 8 + brow) * QP + ks * 16 + bkoff)) * 2;
                ldm_x2(kh, ka);
                ldm_x2(kl, ka + (uint32_t)CHE * 2);
                mma_bf16(s[nt], qh, kh);
                mma_bf16(s[nt], qh, kl);
                mma_bf16(s[nt], ql, kh);
            }
        }

        // ---- mask ----
        const uint32_t widx = (uint32_t)(c * 2);
        const uint2 mw0 = *(const uint2*)(g_mbits + mrow0 + widx);
        const uint2 mw1 = *(const uint2*)(g_mbits + mrow0 + 8 * (S_/32) + widx);
        #pragma unroll
        for (int nt = 0; nt < 8; nt++) {
            const int sh = ((nt * 8) & 31) + (lane & 3) * 2;
            const uint32_t w0 = (nt < 4) ? mw0.x : mw0.y;
            const uint32_t w1 = (nt < 4) ? mw1.x : mw1.y;
            if (!((w0 >> sh) & 1))       s[nt][0] = -1e9f;
            if (!((w0 >> (sh + 1)) & 1)) s[nt][1] = -1e9f;
            if (!((w1 >> sh) & 1))       s[nt][2] = -1e9f;
            if (!((w1 >> (sh + 1)) & 1)) s[nt][3] = -1e9f;
        }

        // ---- online softmax in exp2 domain (rows r and r+8) ----
        float mx0 = -1e30f, mx1 = -1e30f;
        #pragma unroll
        for (int nt = 0; nt < 8; nt++) {
            mx0 = fmaxf(mx0, fmaxf(s[nt][0], s[nt][1]));
            mx1 = fmaxf(mx1, fmaxf(s[nt][2], s[nt][3]));
        }
        mx0 = fmaxf(mx0, __shfl_xor_sync(0xffffffffu, mx0, 1));
        mx0 = fmaxf(mx0, __shfl_xor_sync(0xffffffffu, mx0, 2));
        mx1 = fmaxf(mx1, __shfl_xor_sync(0xffffffffu, mx1, 1));
        mx1 = fmaxf(mx1, __shfl_xor_sync(0xffffffffu, mx1, 2));

        const float mn0 = fmaxf(m0, mx0);
        const float mn1 = fmaxf(m1, mx1);
        const float a0 = ex2f(m0 - mn0);
        const float a1 = ex2f(m1 - mn1);
        m0 = mn0; m1 = mn1;

        float s0 = 0.f, s1 = 0.f;
        #pragma unroll
        for (int nt = 0; nt < 8; nt++) {
            s[nt][0] = ex2f(s[nt][0] - mn0); s0 += s[nt][0];
            s[nt][1] = ex2f(s[nt][1] - mn0); s0 += s[nt][1];
            s[nt][2] = ex2f(s[nt][2] - mn1); s1 += s[nt][2];
            s[nt][3] = ex2f(s[nt][3] - mn1); s1 += s[nt][3];
        }
        s0 += __shfl_xor_sync(0xffffffffu, s0, 1);
        s0 += __shfl_xor_sync(0xffffffffu, s0, 2);
        s1 += __shfl_xor_sync(0xffffffffu, s1, 1);
        s1 += __shfl_xor_sync(0xffffffffu, s1, 2);
        l0 = l0 * a0 + s0;
        l1 = l1 * a1 + s1;

        #pragma unroll
        for (int nt = 0; nt < 8; nt++) {
            out[nt][0] *= a0; out[nt][1] *= a0;
            out[nt][2] *= a1; out[nt][3] *= a1;
        }

        // ---- out += P V (P from S fragments, no smem roundtrip) ----
        #pragma unroll
        for (int j = 0; j < 4; j++) {
            uint32_t ah[4], al[4];
            split2(s[2*j][0],   s[2*j][1],   ah[0], al[0]);
            split2(s[2*j][2],   s[2*j][3],   ah[1], al[1]);
            split2(s[2*j+1][0], s[2*j+1][1], ah[2], al[2]);
            split2(s[2*j+1][2], s[2*j+1][3], ah[3], al[3]);
            #pragma unroll
            for (int nt = 0; nt < 8; nt++) {
                uint32_t vh[2], vl[2];
                const uint32_t va = sb +
                    (kb + (uint32_t)(2 * CHE + (nt * 8 + brow) * QP + j * 16 + bkoff)) * 2;
                ldm_x2(vh, va);
                ldm_x2(vl, va + (uint32_t)CHE * 2);
                mma_bf16(out[nt], ah, vh);
                mma_bf16(out[nt], ah, vl);
                mma_bf16(out[nt], al, vh);
            }
        }
        __syncthreads();
    }

    // ---- epilogue: normalize, split, store bf16 hi/lo into g_xhi/g_xlo ----
    const float i0 = 1.0f / l0;
    const float i1 = 1.0f / l1;
    const int qg = q0 + wid * 16 + r;
    #pragma unroll
    for (int nt = 0; nt < 8; nt++) {
        const int d = nt * 8 + (lane & 3) * 2;
        const size_t o0 = ((size_t)b * S_ + qg) * D_ + h * HD_ + d;
        const size_t o1 = o0 + 8 * D_;
        uint32_t hw, lw;
        split2(out[nt][0] * i0, out[nt][1] * i0, hw, lw);
        *(uint32_t*)&g_xhi[o0] = hw;
        *(uint32_t*)&g_xlo[o0] = lw;
        split2(out[nt][2] * i1, out[nt][3] * i1, hw, lw);
        *(uint32_t*)&g_xhi[o1] = hw;
        *(uint32_t*)&g_xlo[o1] = lw;
    }
}

// ---------------------------------------------------------------------------
extern "C" void kernel_launch(void* const* d_in, const int* in_sizes, int n_in,
                              void* d_out, int out_size)
{
    const float* x  = (const float*)d_in[0];
    const int*   Mm = (const int*)  d_in[1];
    const float* Wq = (const float*)d_in[2];
    const float* Wk = (const float*)d_in[3];
    const float* Wv = (const float*)d_in[4];
    const float* Wo = (const float*)d_in[5];
    const float* bo = (const float*)d_in[6];
    float* out = (float*)d_out;

    __nv_bfloat16 *xhiPtr = nullptr, *xloPtr = nullptr;
    cudaGetSymbolAddress((void**)&xhiPtr, g_xhi);
    cudaGetSymbolAddress((void**)&xloPtr, g_xlo);

    const int gemm_smem = 2 * 4 * TILE_ELT * 2;             // 81920 B
    cudaFuncSetAttribute(tgemm_kernel<0>,
                         cudaFuncAttributeMaxDynamicSharedMemorySize, gemm_smem);
    cudaFuncSetAttribute(tgemm_kernel<1>,
                         cudaFuncAttributeMaxDynamicSharedMemorySize, gemm_smem);
    const int attn_smem = (2 * QSZ + 8 * CHE) * 2;          // 147456 B
    cudaFuncSetAttribute(attn_tc,
                         cudaFuncAttributeMaxDynamicSharedMemorySize, attn_smem);

    // 1) split input x and all weights to hi/lo bf16
    split_x_kernel<<<NELEM/1024, 256>>>(x, xhiPtr, xloPtr);
    split_w_kernel<<<dim3((D_*D_)/1024, 4), 256>>>(Wq, Wk, Wv, Wo);
    // 2) QKV projections (HMMA); epilogue splits Q/K to bf16, V stays fp32
    tgemm_kernel<0><<<dim3(8, 32, 3), 256, gemm_smem>>>(xhiPtr, xloPtr, nullptr, nullptr);
    // 3) pack mask bits; transpose+split V
    packmask_kernel<<<(B_*S_)/8, 256>>>(Mm);
    vtrans_kernel<<<dim3(S_/64, B_*H_), 256>>>();
    // 4) tensor-core flash attention -> g_xhi/g_xlo [B,S,D]
    attn_tc<<<dim3(S_/QROWS, B_*H_), 512, attn_smem>>>();
    // 5) output projection + bias (HMMA)
    tgemm_kernel<1><<<dim3(8, 32, 1), 256, gemm_smem>>>(xhiPtr, xloPtr, bo, out);
}

// round 7
// speedup vs baseline: 3.0127x; 1.0635x over previous
#include <cuda_runtime.h>
#include <cuda_bf16.h>
#include <cstdint>

#define B_  2
#define S_  2048
#define D_  1024
#define H_  16
#define HD_ 64
#define NELEM (B_*S_*D_)      // 4194304

// Scratch (allocation-free rule: __device__ globals)
__device__ __align__(16) float g_V[NELEM];                // [B,H,S,HD] fp32
__device__ __align__(16) __nv_bfloat16 g_xhi[NELEM];      // activations hi
__device__ __align__(16) __nv_bfloat16 g_xlo[NELEM];      // activations lo
__device__ __align__(16) __nv_bfloat16 g_whi[4*D_*D_];    // Wq,Wk,Wv,Wo hi
__device__ __align__(16) __nv_bfloat16 g_wlo[4*D_*D_];    // Wq,Wk,Wv,Wo lo
__device__ __align__(16) __nv_bfloat16 g_Qhi[NELEM];      // [B,H,S,HD] (scaled by 0.125*log2e)
__device__ __align__(16) __nv_bfloat16 g_Qlo[NELEM];
__device__ __align__(16) __nv_bfloat16 g_Khi[NELEM];      // [B,H,S,HD]
__device__ __align__(16) __nv_bfloat16 g_Klo[NELEM];
__device__ __align__(16) __nv_bfloat16 g_Vthi[NELEM];     // [B,H,HD,S] (transposed)
__device__ __align__(16) __nv_bfloat16 g_Vtlo[NELEM];
__device__ __align__(16) uint32_t g_mbits[B_*S_*(S_/32)]; // packed mask bits

// ===========================================================================
// PTX helpers (baseline PTX only — compiles under compute_103)
// ===========================================================================
__device__ __forceinline__ uint32_t smem_u32(const void* p) {
    uint32_t a;
    asm("{ .reg .u64 t; cvta.to.shared.u64 t, %1; cvt.u32.u64 %0, t; }"
        : "=r"(a) : "l"(p));
    return a;
}
__device__ __forceinline__ void cp16(uint32_t saddr, const void* g) {
    asm volatile("cp.async.cg.shared.global [%0], [%1], 16;"
                 :: "r"(saddr), "l"(g) : "memory");
}
__device__ __forceinline__ void ldm_x4(uint32_t* r, uint32_t addr) {
    asm volatile("ldmatrix.sync.aligned.m8n8.x4.shared.b16 {%0,%1,%2,%3}, [%4];"
        : "=r"(r[0]), "=r"(r[1]), "=r"(r[2]), "=r"(r[3]) : "r"(addr));
}
__device__ __forceinline__ void mma_bf16(float* c, const uint32_t* a, const uint32_t* b) {
    asm volatile("mma.sync.aligned.m16n8k16.row.col.f32.bf16.bf16.f32 "
        "{%0,%1,%2,%3}, {%4,%5,%6,%7}, {%8,%9}, {%0,%1,%2,%3};"
        : "+f"(c[0]), "+f"(c[1]), "+f"(c[2]), "+f"(c[3])
        : "r"(a[0]), "r"(a[1]), "r"(a[2]), "r"(a[3]), "r"(b[0]), "r"(b[1]));
}
__device__ __forceinline__ float ex2f(float x) {
    float r;
    asm("ex2.approx.f32 %0, %1;" : "=f"(r) : "f"(x));
    return r;
}

// Fast fp32 pair -> packed hi (truncated bf16) + packed lo (rounded remainder)
__device__ __forceinline__ void split2(float x, float y, uint32_t& h, uint32_t& l) {
    const uint32_t xb = __float_as_uint(x) & 0xFFFF0000u;
    const uint32_t yb = __float_as_uint(y) & 0xFFFF0000u;
    h = (xb >> 16) | yb;                       // {lo16=bf16(x), hi16=bf16(y)}
    const float lx = x - __uint_as_float(xb);  // exact
    const float ly = y - __uint_as_float(yb);  // exact
    asm("cvt.rn.bf16x2.f32 %0, %1, %2;" : "=r"(l) : "f"(ly), "f"(lx));
}

// ---------------------------------------------------------------------------
// split kernels
// ---------------------------------------------------------------------------
__global__ __launch_bounds__(256) void split_x_kernel(
    const float* __restrict__ src,
    __nv_bfloat16* __restrict__ hi, __nv_bfloat16* __restrict__ lo)
{
    const int i = (blockIdx.x * 256 + threadIdx.x) * 4;
    const float4 v = *(const float4*)(src + i);
    uint2 hv, lv;
    split2(v.x, v.y, hv.x, lv.x);
    split2(v.z, v.w, hv.y, lv.y);
    *(uint2*)(hi + i) = hv;
    *(uint2*)(lo + i) = lv;
}

__global__ __launch_bounds__(256) void split_w_kernel(
    const float* __restrict__ w0, const float* __restrict__ w1,
    const float* __restrict__ w2, const float* __restrict__ w3)
{
    const int wsel = blockIdx.y;
    const float* src = (wsel == 0) ? w0 : (wsel == 1) ? w1 : (wsel == 2) ? w2 : w3;
    const int i = (blockIdx.x * 256 + threadIdx.x) * 4;
    const float4 v = *(const float4*)(src + i);
    uint2 hv, lv;
    split2(v.x, v.y, hv.x, lv.x);
    split2(v.z, v.w, hv.y, lv.y);
    const size_t o = (size_t)wsel * D_ * D_ + i;
    *(uint2*)(g_whi + o) = hv;
    *(uint2*)(g_wlo + o) = lv;
}

// ---------------------------------------------------------------------------
// mask pack: bit j of word w of row (b,q) = (M[b,q,w*32+j] != 0)
// ---------------------------------------------------------------------------
__global__ __launch_bounds__(256) void packmask_kernel(const int* __restrict__ M)
{
    const int lane = threadIdx.x & 31;
    const int row = blockIdx.x * 8 + (threadIdx.x >> 5);   // 0..4095
    const int* src = M + (size_t)row * S_;
    uint32_t* dst = g_mbits + row * (S_/32);
    for (int w = 0; w < S_/32; w++) {
        const int v = src[w * 32 + lane];
        const uint32_t bits = __ballot_sync(0xffffffffu, v != 0);
        if (lane == 0) dst[w] = bits;
    }
}

// ---------------------------------------------------------------------------
// V transpose+split: g_V [B,H,S,64] fp32 -> g_Vthi/lo [B,H,64,S] bf16
// ---------------------------------------------------------------------------
__global__ __launch_bounds__(256) void vtrans_kernel()
{
    __shared__ float t[64][65];
    const int bh = blockIdx.y;
    const int k0 = blockIdx.x * 64;
    const float* src = g_V + ((size_t)bh * S_ + k0) * HD_;
    const int tid = threadIdx.x;
    #pragma unroll
    for (int it = 0; it < 4; it++) {
        const int r = (tid >> 4) + it * 16;
        const int c = (tid & 15) * 4;
        const float4 v = *(const float4*)(src + r * HD_ + c);
        t[r][c] = v.x; t[r][c+1] = v.y; t[r][c+2] = v.z; t[r][c+3] = v.w;
    }
    __syncthreads();
    #pragma unroll
    for (int it = 0; it < 4; it++) {
        const int d  = (tid >> 4) + it * 16;
        const int k4 = (tid & 15) * 4;
        uint32_t h0, l0, h1, l1;
        split2(t[k4][d],   t[k4+1][d], h0, l0);
        split2(t[k4+2][d], t[k4+3][d], h1, l1);
        const size_t o = ((size_t)bh * HD_ + d) * S_ + k0 + k4;
        *(uint2*)&g_Vthi[o] = make_uint2(h0, h1);
        *(uint2*)&g_Vtlo[o] = make_uint2(l0, l1);
    }
}

// ===========================================================================
// HMMA GEMM: C[m,n] = sum_k A[m,k]*W[n,k], 3-term bf16 split.
// 128x128 block, 8 warps, KC=32 double-buffered. B fragments loaded as x4
// n-tile PAIRS; MMA terms reordered (term-outer) to break accumulator RAW
// chains. 2 CTAs/SM.
// MODE 0: z=0 -> Q (scaled by 0.125*log2e, split), z=1 -> K (split), z=2 -> V fp32
// MODE 1: W = Wo (idx 3); out = A@Wo^T + bias -> Cout
// ===========================================================================
#define KC 32
#define NCH 32
#define AP 40
#define TILE_ELT (128*AP)

template<int MODE>
__global__ __launch_bounds__(256, 2) void tgemm_kernel(
    const __nv_bfloat16* __restrict__ Ahi_g,
    const __nv_bfloat16* __restrict__ Alo_g,
    const float* __restrict__ bias,
    float* __restrict__ Cout)
{
    extern __shared__ __nv_bfloat16 smem[];
    const uint32_t sb = smem_u32(smem);

    const int tid = threadIdx.x;
    const int wid = tid >> 5, lane = tid & 31;
    const int m0 = blockIdx.y * 128;
    const int n0 = blockIdx.x * 128;
    const int widx = (MODE == 0) ? blockIdx.z : 3;
    const __nv_bfloat16* Bhi_g = g_whi + (size_t)widx * D_ * D_;
    const __nv_bfloat16* Blo_g = g_wlo + (size_t)widx * D_ * D_;

    const int lrow0 = tid >> 2;
    const int lcol  = (tid & 3) * 8;

    const int arow  = (lane & 7) + ((lane >> 3) & 1) * 8;
    const int akoff = ((lane >> 4) & 1) * 8;
    // x4 pair-load lane mapping for B: tile = lane>>4, khalf = (lane>>3)&1, row = lane&7
    const int btile = lane >> 4;
    const int bk    = (lane >> 3) & 1;
    const int br    = lane & 7;
    const int wm = (wid & 1) * 64;
    const int wn = (wid >> 1) * 32;

    float acc[4][4][4];
    #pragma unroll
    for (int mt = 0; mt < 4; mt++)
        #pragma unroll
        for (int nt = 0; nt < 4; nt++)
            #pragma unroll
            for (int j = 0; j < 4; j++) acc[mt][nt][j] = 0.f;

    auto prefetch = [&](int c) {
        const int buf = c & 1;
        const int kc = c * KC;
        const uint32_t s0 = sb + (uint32_t)(buf * 4 * TILE_ELT) * 2;
        const uint32_t soff = (uint32_t)(lrow0 * AP + lcol) * 2;
        {
            const __nv_bfloat16* g = Ahi_g + (size_t)(m0 + lrow0) * 1024 + kc + lcol;
            cp16(s0 + 0 * TILE_ELT * 2 + soff, g);
            cp16(s0 + 0 * TILE_ELT * 2 + soff + 64 * AP * 2, g + 64 * 1024);
        }
        {
            const __nv_bfloat16* g = Alo_g + (size_t)(m0 + lrow0) * 1024 + kc + lcol;
            cp16(s0 + 1 * TILE_ELT * 2 + soff, g);
            cp16(s0 + 1 * TILE_ELT * 2 + soff + 64 * AP * 2, g + 64 * 1024);
        }
        {
            const __nv_bfloat16* g = Bhi_g + (size_t)(n0 + lrow0) * 1024 + kc + lcol;
            cp16(s0 + 2 * TILE_ELT * 2 + soff, g);
            cp16(s0 + 2 * TILE_ELT * 2 + soff + 64 * AP * 2, g + 64 * 1024);
        }
        {
            const __nv_bfloat16* g = Blo_g + (size_t)(n0 + lrow0) * 1024 + kc + lcol;
            cp16(s0 + 3 * TILE_ELT * 2 + soff, g);
            cp16(s0 + 3 * TILE_ELT * 2 + soff + 64 * AP * 2, g + 64 * 1024);
        }
        asm volatile("cp.async.commit_group;" ::: "memory");
    };

    prefetch(0);

    for (int c = 0; c < NCH; c++) {
        if (c + 1 < NCH) {
            prefetch(c + 1);
            asm volatile("cp.async.wait_group 1;" ::: "memory");
        } else {
            asm volatile("cp.async.wait_group 0;" ::: "memory");
        }
        __syncthreads();

        const int buf = c & 1;
        const uint32_t base = sb + (uint32_t)(buf * 4 * TILE_ELT) * 2;
        const uint32_t aAhi = base;
        const uint32_t aAlo = base + (uint32_t)TILE_ELT * 2;
        const uint32_t aBhi = base + (uint32_t)TILE_ELT * 4;
        const uint32_t aBlo = base + (uint32_t)TILE_ELT * 6;

        #pragma unroll
        for (int ks = 0; ks < 2; ks++) {
            const int k0 = ks * 16;
            uint32_t bh[4][2], bl[4][2];
            #pragma unroll
            for (int p = 0; p < 2; p++) {
                const uint32_t ba = (uint32_t)(
                    (wn + (p * 2 + btile) * 8 + br) * AP + k0 + bk * 8) * 2;
                ldm_x4(&bh[p*2][0], aBhi + ba);
                ldm_x4(&bl[p*2][0], aBlo + ba);
            }
            #pragma unroll
            for (int mt = 0; mt < 4; mt++) {
                const uint32_t aa =
                    (uint32_t)((wm + mt * 16 + arow) * AP + k0 + akoff) * 2;
                uint32_t ah[4], al[4];
                ldm_x4(ah, aAhi + aa);
                ldm_x4(al, aAlo + aa);
                #pragma unroll
                for (int nt = 0; nt < 4; nt++) mma_bf16(acc[mt][nt], ah, bh[nt]);
                #pragma unroll
                for (int nt = 0; nt < 4; nt++) mma_bf16(acc[mt][nt], ah, bl[nt]);
                #pragma unroll
                for (int nt = 0; nt < 4; nt++) mma_bf16(acc[mt][nt], al, bh[nt]);
            }
        }
        __syncthreads();
    }

    // ---- epilogue ----
    const int r_lo  = lane >> 2;
    const int coff  = (lane & 3) * 2;
    // Q scale folds softmax 1/sqrt(64) AND log2(e) for exp2-based softmax
    const float scale = (MODE == 0 && blockIdx.z == 0) ? 0.125f * 1.44269504f : 1.0f;

    #pragma unroll
    for (int mt = 0; mt < 4; mt++) {
        const int r0 = m0 + wm + mt * 16 + r_lo;
        const int r1 = r0 + 8;
        #pragma unroll
        for (int nt = 0; nt < 4; nt++) {
            const int cg = n0 + wn + nt * 8 + coff;
            float2 v0 = make_float2(acc[mt][nt][0] * scale, acc[mt][nt][1] * scale);
            float2 v1 = make_float2(acc[mt][nt][2] * scale, acc[mt][nt][3] * scale);
            if (MODE == 0) {
                const int h = cg >> 6, hd = cg & 63;
                #pragma unroll
                for (int half = 0; half < 2; half++) {
                    const int rr = half ? r1 : r0;
                    const float2 v = half ? v1 : v0;
                    const int bb_ = rr >> 11, ss = rr & 2047;
                    const size_t o = (((size_t)(bb_ * H_ + h)) * S_ + ss) * HD_ + hd;
                    if (blockIdx.z == 2) {
                        *(float2*)&g_V[o] = v;
                    } else {
                        uint32_t hw, lw;
                        split2(v.x, v.y, hw, lw);
                        if (blockIdx.z == 0) {
                            *(uint32_t*)&g_Qhi[o] = hw;
                            *(uint32_t*)&g_Qlo[o] = lw;
                        } else {
                            *(uint32_t*)&g_Khi[o] = hw;
                            *(uint32_t*)&g_Klo[o] = lw;
                        }
                    }
                }
            } else {
                const float2 bb = *(const float2*)&bias[cg];
                v0.x += bb.x; v0.y += bb.y;
                v1.x += bb.x; v1.y += bb.y;
                *(float2*)&Cout[(size_t)r0 * 1024 + cg] = v0;
                *(float2*)&Cout[(size_t)r1 * 1024 + cg] = v1;
            }
        }
    }
}

// ===========================================================================
// Tensor-core flash attention, 512 threads / 256 queries per CTA.
// K/V fragments loaded as x4 n-tile PAIRS; MMA terms reordered term-outer
// (in two half-groups of 4 accumulators) to break RAW chains.
// ===========================================================================
#define QP 72
#define QROWS 256
#define QSZ (QROWS*QP)
#define CHE (64*QP)

__global__ __launch_bounds__(512) void attn_tc()
{
    extern __shared__ __nv_bfloat16 sm[];
    const uint32_t sb = smem_u32(sm);
    const int tid = threadIdx.x, wid = tid >> 5, lane = tid & 31;
    const int bh = blockIdx.y, b = bh >> 4, h = bh & 15;
    const int q0 = blockIdx.x * QROWS;

    const __nv_bfloat16* Qhi_g = g_Qhi + ((size_t)bh * S_ + q0) * HD_;
    const __nv_bfloat16* Qlo_g = g_Qlo + ((size_t)bh * S_ + q0) * HD_;
    const __nv_bfloat16* Khi_g = g_Khi + (size_t)bh * S_ * HD_;
    const __nv_bfloat16* Klo_g = g_Klo + (size_t)bh * S_ * HD_;
    const __nv_bfloat16* Vhi_g = g_Vthi + (size_t)bh * HD_ * S_;
    const __nv_bfloat16* Vlo_g = g_Vtlo + (size_t)bh * HD_ * S_;

    // Q tiles (hi, lo) -> smem once; joins cp.async group 0
    #pragma unroll
    for (int t = 0; t < 8; t++) {
        const int i = tid + t * 512;                 // 0..4095
        const int mat = i >> 11, rem = i & 2047, row = rem >> 3, c16 = rem & 7;
        const __nv_bfloat16* g = (mat ? Qlo_g : Qhi_g) + row * HD_ + c16 * 8;
        cp16(sb + (uint32_t)(mat * QSZ + row * QP) * 2 + c16 * 16, g);
    }

    auto prefetch = [&](int c) {
        const int buf = c & 1;
        const int k0 = c * 64;
        const uint32_t base = (uint32_t)(2 * QSZ + buf * 4 * CHE);
        #pragma unroll
        for (int t = 0; t < 4; t++) {
            const int i = tid + t * 512;             // 0..2047
            const int mat = i >> 9, rem = i & 511, row = rem >> 3, c16 = rem & 7;
            const __nv_bfloat16* g;
            if (mat == 0)      g = Khi_g + (size_t)(k0 + row) * HD_ + c16 * 8;
            else if (mat == 1) g = Klo_g + (size_t)(k0 + row) * HD_ + c16 * 8;
            else if (mat == 2) g = Vhi_g + (size_t)row * S_ + k0 + c16 * 8;
            else               g = Vlo_g + (size_t)row * S_ + k0 + c16 * 8;
            cp16(sb + (base + (uint32_t)(mat * CHE + row * QP)) * 2 + c16 * 16, g);
        }
        asm volatile("cp.async.commit_group;" ::: "memory");
    };

    prefetch(0);

    const int arow  = (lane & 7) + ((lane >> 3) & 1) * 8;
    const int akoff = ((lane >> 4) & 1) * 8;
    // x4 pair-load mapping: tile = lane>>4, khalf = (lane>>3)&1, row = lane&7
    const int btile = lane >> 4;
    const int bk    = (lane >> 3) & 1;
    const int br    = lane & 7;
    const int r = lane >> 2;

    float out[8][4];
    #pragma unroll
    for (int nt = 0; nt < 8; nt++)
        #pragma unroll
        for (int j = 0; j < 4; j++) out[nt][j] = 0.f;
    float m0 = -1e30f, m1 = -1e30f, l0 = 0.f, l1 = 0.f;

    const uint32_t mrow0 = ((uint32_t)b * S_ + q0 + wid * 16 + r) * (S_/32);

    for (int c = 0; c < 32; c++) {
        if (c + 1 < 32) {
            prefetch(c + 1);
            asm volatile("cp.async.wait_group 1;" ::: "memory");
        } else {
            asm volatile("cp.async.wait_group 0;" ::: "memory");
        }
        __syncthreads();

        const int buf = c & 1;
        const uint32_t kb = (uint32_t)(2 * QSZ + buf * 4 * CHE);

        // ---- S = Q K^T (already in log2e domain via Q scale) ----
        float s[8][4];
        #pragma unroll
        for (int nt = 0; nt < 8; nt++)
            #pragma unroll
            for (int j = 0; j < 4; j++) s[nt][j] = 0.f;

        #pragma unroll
        for (int ks = 0; ks < 4; ks++) {
            uint32_t qh[4], ql[4];
            const uint32_t qa =
                (uint32_t)((wid * 16 + arow) * QP + ks * 16 + akoff) * 2;
            ldm_x4(qh, sb + qa);
            ldm_x4(ql, sb + (uint32_t)QSZ * 2 + qa);
            #pragma unroll
            for (int half = 0; half < 2; half++) {
                uint32_t kh[4][2], kl[4][2];
                #pragma unroll
                for (int p = 0; p < 2; p++) {
                    const int t0 = half * 4 + p * 2;
                    const uint32_t ka = sb + (kb + (uint32_t)(
                        ((t0 + btile) * 8 + br) * QP + ks * 16 + bk * 8)) * 2;
                    ldm_x4(&kh[p*2][0], ka);
                    ldm_x4(&kl[p*2][0], ka + (uint32_t)CHE * 2);
                }
                #pragma unroll
                for (int q = 0; q < 4; q++) mma_bf16(s[half*4+q], qh, kh[q]);
                #pragma unroll
                for (int q = 0; q < 4; q++) mma_bf16(s[half*4+q], qh, kl[q]);
                #pragma unroll
                for (int q = 0; q < 4; q++) mma_bf16(s[half*4+q], ql, kh[q]);
            }
        }

        // ---- mask ----
        const uint32_t widx = (uint32_t)(c * 2);
        const uint2 mw0 = *(const uint2*)(g_mbits + mrow0 + widx);
        const uint2 mw1 = *(const uint2*)(g_mbits + mrow0 + 8 * (S_/32) + widx);
        #pragma unroll
        for (int nt = 0; nt < 8; nt++) {
            const int sh = ((nt * 8) & 31) + (lane & 3) * 2;
            const uint32_t w0 = (nt < 4) ? mw0.x : mw0.y;
            const uint32_t w1 = (nt < 4) ? mw1.x : mw1.y;
            if (!((w0 >> sh) & 1))       s[nt][0] = -1e9f;
            if (!((w0 >> (sh + 1)) & 1)) s[nt][1] = -1e9f;
            if (!((w1 >> sh) & 1))       s[nt][2] = -1e9f;
            if (!((w1 >> (sh + 1)) & 1)) s[nt][3] = -1e9f;
        }

        // ---- online softmax in exp2 domain (rows r and r+8) ----
        float mx0 = -1e30f, mx1 = -1e30f;
        #pragma unroll
        for (int nt = 0; nt < 8; nt++) {
            mx0 = fmaxf(mx0, fmaxf(s[nt][0], s[nt][1]));
            mx1 = fmaxf(mx1, fmaxf(s[nt][2], s[nt][3]));
        }
        mx0 = fmaxf(mx0, __shfl_xor_sync(0xffffffffu, mx0, 1));
        mx0 = fmaxf(mx0, __shfl_xor_sync(0xffffffffu, mx0, 2));
        mx1 = fmaxf(mx1, __shfl_xor_sync(0xffffffffu, mx1, 1));
        mx1 = fmaxf(mx1, __shfl_xor_sync(0xffffffffu, mx1, 2));

        const float mn0 = fmaxf(m0, mx0);
        const float mn1 = fmaxf(m1, mx1);
        const float a0 = ex2f(m0 - mn0);
        const float a1 = ex2f(m1 - mn1);
        m0 = mn0; m1 = mn1;

        float s0 = 0.f, s1 = 0.f;
        #pragma unroll
        for (int nt = 0; nt < 8; nt++) {
            s[nt][0] = ex2f(s[nt][0] - mn0); s0 += s[nt][0];
            s[nt][1] = ex2f(s[nt][1] - mn0); s0 += s[nt][1];
            s[nt][2] = ex2f(s[nt][2] - mn1); s1 += s[nt][2];
            s[nt][3] = ex2f(s[nt][3] - mn1); s1 += s[nt][3];
        }
        s0 += __shfl_xor_sync(0xffffffffu, s0, 1);
        s0 += __shfl_xor_sync(0xffffffffu, s0, 2);
        s1 += __shfl_xor_sync(0xffffffffu, s1, 1);
        s1 += __shfl_xor_sync(0xffffffffu, s1, 2);
        l0 = l0 * a0 + s0;
        l1 = l1 * a1 + s1;

        #pragma unroll
        for (int nt = 0; nt < 8; nt++) {
            out[nt][0] *= a0; out[nt][1] *= a0;
            out[nt][2] *= a1; out[nt][3] *= a1;
        }

        // ---- out += P V (P from S fragments, no smem roundtrip) ----
        #pragma unroll
        for (int j = 0; j < 4; j++) {
            uint32_t ah[4], al[4];
            split2(s[2*j][0],   s[2*j][1],   ah[0], al[0]);
            split2(s[2*j][2],   s[2*j][3],   ah[1], al[1]);
            split2(s[2*j+1][0], s[2*j+1][1], ah[2], al[2]);
            split2(s[2*j+1][2], s[2*j+1][3], ah[3], al[3]);
            #pragma unroll
            for (int half = 0; half < 2; half++) {
                uint32_t vh[4][2], vl[4][2];
                #pragma unroll
                for (int p = 0; p < 2; p++) {
                    const int t0 = half * 4 + p * 2;
                    const uint32_t va = sb + (kb + (uint32_t)(
                        2 * CHE + ((t0 + btile) * 8 + br) * QP + j * 16 + bk * 8)) * 2;
                    ldm_x4(&vh[p*2][0], va);
                    ldm_x4(&vl[p*2][0], va + (uint32_t)CHE * 2);
                }
                #pragma unroll
                for (int q = 0; q < 4; q++) mma_bf16(out[half*4+q], ah, vh[q]);
                #pragma unroll
                for (int q = 0; q < 4; q++) mma_bf16(out[half*4+q], ah, vl[q]);
                #pragma unroll
                for (int q = 0; q < 4; q++) mma_bf16(out[half*4+q], al, vh[q]);
            }
        }
        __syncthreads();
    }

    // ---- epilogue: normalize, split, store bf16 hi/lo into g_xhi/g_xlo ----
    const float i0 = 1.0f / l0;
    const float i1 = 1.0f / l1;
    const int qg = q0 + wid * 16 + r;
    #pragma unroll
    for (int nt = 0; nt < 8; nt++) {
        const int d = nt * 8 + (lane & 3) * 2;
        const size_t o0 = ((size_t)b * S_ + qg) * D_ + h * HD_ + d;
        const size_t o1 = o0 + 8 * D_;
        uint32_t hw, lw;
        split2(out[nt][0] * i0, out[nt][1] * i0, hw, lw);
        *(uint32_t*)&g_xhi[o0] = hw;
        *(uint32_t*)&g_xlo[o0] = lw;
        split2(out[nt][2] * i1, out[nt][3] * i1, hw, lw);
        *(uint32_t*)&g_xhi[o1] = hw;
        *(uint32_t*)&g_xlo[o1] = lw;
    }
}

// ---------------------------------------------------------------------------
extern "C" void kernel_launch(void* const* d_in, const int* in_sizes, int n_in,
                              void* d_out, int out_size)
{
    const float* x  = (const float*)d_in[0];
    const int*   Mm = (const int*)  d_in[1];
    const float* Wq = (const float*)d_in[2];
    const float* Wk = (const float*)d_in[3];
    const float* Wv = (const float*)d_in[4];
    const float* Wo = (const float*)d_in[5];
    const float* bo = (const float*)d_in[6];
    float* out = (float*)d_out;

    __nv_bfloat16 *xhiPtr = nullptr, *xloPtr = nullptr;
    cudaGetSymbolAddress((void**)&xhiPtr, g_xhi);
    cudaGetSymbolAddress((void**)&xloPtr, g_xlo);

    const int gemm_smem = 2 * 4 * TILE_ELT * 2;             // 81920 B
    cudaFuncSetAttribute(tgemm_kernel<0>,
                         cudaFuncAttributeMaxDynamicSharedMemorySize, gemm_smem);
    cudaFuncSetAttribute(tgemm_kernel<1>,
                         cudaFuncAttributeMaxDynamicSharedMemorySize, gemm_smem);
    const int attn_smem = (2 * QSZ + 8 * CHE) * 2;          // 147456 B
    cudaFuncSetAttribute(attn_tc,
                         cudaFuncAttributeMaxDynamicSharedMemorySize, attn_smem);

    // 1) split input x and all weights to hi/lo bf16
    split_x_kernel<<<NELEM/1024, 256>>>(x, xhiPtr, xloPtr);
    split_w_kernel<<<dim3((D_*D_)/1024, 4), 256>>>(Wq, Wk, Wv, Wo);
    // 2) QKV projections (HMMA); epilogue splits Q/K to bf16, V stays fp32
    tgemm_kernel<0><<<dim3(8, 32, 3), 256, gemm_smem>>>(xhiPtr, xloPtr, nullptr, nullptr);
    // 3) pack mask bits; transpose+split V
    packmask_kernel<<<(B_*S_)/8, 256>>>(Mm);
    vtrans_kernel<<<dim3(S_/64, B_*H_), 256>>>();
    // 4) tensor-core flash attention -> g_xhi/g_xlo [B,S,D]
    attn_tc<<<dim3(S_/QROWS, B_*H_), 512, attn_smem>>>();
    // 5) output projection + bias (HMMA)
    tgemm_kernel<1><<<dim3(8, 32, 1), 256, gemm_smem>>>(xhiPtr, xloPtr, bo, out);
}